// round 1
// baseline (speedup 1.0000x reference)
#include <cuda_runtime.h>
#include <math.h>

// ---------------- problem constants ----------------
#define NB    64
#define NSEQ  198
#define NTOK  (NB*NSEQ)      // 12672
#define NPAT  (NB*196)       // 12544
#define CDIM  768
#define NHEAD 12
#define HD    64

// ---------------- scratch (device globals; no allocs allowed) ----------------
__device__ float g_t   [(size_t)NTOK*CDIM];       // token stream
__device__ float g_a   [(size_t)NTOK*CDIM];       // LN out / im2col
__device__ float g_qkv [(size_t)NTOK*3*CDIM];     // qkv
__device__ float g_attn[(size_t)NB*NHEAD*NSEQ*NSEQ];
__device__ float g_o   [(size_t)NTOK*CDIM];       // attn out / patch gemm out
__device__ float g_h   [(size_t)NTOK*4*CDIM];     // mlp hidden
__device__ float g_mask[(size_t)12*NB*NSEQ];
__device__ float g_sfeat[(size_t)NB*6912];

// ---------------- generic SGEMM-NT: C[M,N] = A[M,K] * B[N,K]^T ----------------
#define BM 128
#define BN 128
#define BK 8
enum { EP_NONE=0, EP_BIAS=1, EP_BIAS_RES=2, EP_BIAS_GELU=3 };

template<int EPI>
__launch_bounds__(256)
__global__ void gemm_nt(const float* __restrict__ A, const float* __restrict__ B,
                        const float* __restrict__ bias, const float* __restrict__ res,
                        float* __restrict__ C, int M, int N, int K)
{
    __shared__ float As[BK][BM];
    __shared__ float Bs[BK][BN];
    const int tid = threadIdx.x;
    const int bm = blockIdx.y * BM;
    const int bn = blockIdx.x * BN;
    const int lr = tid >> 1;
    const int lk = (tid & 1) * 4;
    const int tx = tid & 15, ty = tid >> 4;
    const int r0 = ty * 8, c0 = tx * 8;

    float acc[8][8];
#pragma unroll
    for (int i=0;i<8;i++)
#pragma unroll
        for (int j=0;j<8;j++) acc[i][j]=0.f;

    const int ar = bm + lr;
    const int br = bn + lr;
    const float* Ap = A + (size_t)ar * K + lk;
    const float* Bp = B + (size_t)br * K + lk;
    const bool aok = ar < M;
    const bool bok = br < N;

    for (int k0 = 0; k0 < K; k0 += BK) {
        float4 av = make_float4(0.f,0.f,0.f,0.f);
        float4 bv = make_float4(0.f,0.f,0.f,0.f);
        if (aok) av = *(const float4*)(Ap + k0);
        if (bok) bv = *(const float4*)(Bp + k0);
        As[lk+0][lr]=av.x; As[lk+1][lr]=av.y; As[lk+2][lr]=av.z; As[lk+3][lr]=av.w;
        Bs[lk+0][lr]=bv.x; Bs[lk+1][lr]=bv.y; Bs[lk+2][lr]=bv.z; Bs[lk+3][lr]=bv.w;
        __syncthreads();
#pragma unroll
        for (int kk=0; kk<BK; kk++) {
            float ra[8], rb[8];
            *(float4*)&ra[0] = *(const float4*)&As[kk][r0];
            *(float4*)&ra[4] = *(const float4*)&As[kk][r0+4];
            *(float4*)&rb[0] = *(const float4*)&Bs[kk][c0];
            *(float4*)&rb[4] = *(const float4*)&Bs[kk][c0+4];
#pragma unroll
            for (int i=0;i<8;i++)
#pragma unroll
                for (int j=0;j<8;j++) acc[i][j] = fmaf(ra[i], rb[j], acc[i][j]);
        }
        __syncthreads();
    }

#pragma unroll
    for (int i=0;i<8;i++) {
        int row = bm + r0 + i;
        if (row < M) {
#pragma unroll
            for (int j=0;j<8;j++) {
                int col = bn + c0 + j;
                if (col < N) {
                    float v = acc[i][j];
                    if (EPI == EP_BIAS)      v += bias[col];
                    else if (EPI == EP_BIAS_RES)  v += bias[col] + res[(size_t)row*N + col];
                    else if (EPI == EP_BIAS_GELU) { v += bias[col]; v = 0.5f*v*(1.f + erff(v*0.70710678118654752f)); }
                    C[(size_t)row*N + col] = v;
                }
            }
        }
    }
}

// ---------------- patch im2col (non-overlapping 16x16 patches) ----------------
__global__ void im2col_patch(const float* __restrict__ x, float* __restrict__ A)
{
    int i = blockIdx.x*256 + threadIdx.x;
    if (i >= NPAT*CDIM) return;
    int p = i / CDIM, kidx = i - p*CDIM;
    int b = p / 196, pp = p - b*196;
    int py = pp / 14, px = pp - py*14;
    int c = kidx >> 8;
    int rem = kidx & 255;
    int iy = rem >> 4, ix = rem & 15;
    A[i] = x[(((size_t)b*3 + c)*224 + (py*16+iy))*224 + (px*16+ix)];
}

// ---------------- assemble token stream: cls | patches | loc, + pos ----------------
__global__ void assemble_t(const float* __restrict__ P, const float* __restrict__ cls,
                           const float* __restrict__ loc, const float* __restrict__ pos,
                           const float* __restrict__ loce, float* __restrict__ T)
{
    int i = blockIdx.x*256 + threadIdx.x;
    if (i >= NTOK*CDIM) return;
    int tok = i / CDIM, c = i - tok*CDIM;
    int b = tok / NSEQ, tt = tok - b*NSEQ;
    float v;
    if (tt == 0)          v = cls[c] + pos[c];
    else if (tt == 197)   v = loc[c] + loce[c];
    else                  v = P[((size_t)b*196 + tt-1)*CDIM + c] + pos[(size_t)tt*CDIM + c];
    T[i] = v;
}

// ---------------- layernorm (block per token row of 768) ----------------
__launch_bounds__(256)
__global__ void ln_kernel(const float* __restrict__ X, const float* __restrict__ w,
                          const float* __restrict__ bb, float* __restrict__ Y)
{
    int row = blockIdx.x;
    const float* x = X + (size_t)row * CDIM;
    float* y = Y + (size_t)row * CDIM;
    int tid = threadIdx.x;
    float v0 = x[tid], v1 = x[tid+256], v2 = x[tid+512];
    __shared__ float red[8];
    __shared__ float mrs[2];
    float s = v0+v1+v2;
#pragma unroll
    for (int o=16;o;o>>=1) s += __shfl_xor_sync(0xffffffffu, s, o);
    if ((tid&31)==0) red[tid>>5] = s;
    __syncthreads();
    if (tid==0){ float t=0.f; for(int i=0;i<8;i++) t+=red[i]; mrs[0]=t*(1.f/768.f); }
    __syncthreads();
    float m = mrs[0];
    float d0=v0-m, d1=v1-m, d2=v2-m;
    float q = d0*d0+d1*d1+d2*d2;
#pragma unroll
    for (int o=16;o;o>>=1) q += __shfl_xor_sync(0xffffffffu, q, o);
    __syncthreads();
    if ((tid&31)==0) red[tid>>5] = q;
    __syncthreads();
    if (tid==0){ float t=0.f; for(int i=0;i<8;i++) t+=red[i]; mrs[1]=rsqrtf(t*(1.f/768.f)+1e-5f); }
    __syncthreads();
    float rs = mrs[1];
    y[tid]     = d0*rs*w[tid]     + bb[tid];
    y[tid+256] = d1*rs*w[tid+256] + bb[tid+256];
    y[tid+512] = d2*rs*w[tid+512] + bb[tid+512];
}

// ---------------- attention scores: S = q k^T * scale, per (b,h) block ----------------
#define SMEM_SCORES ((NSEQ*64 + NSEQ*65)*4)
__launch_bounds__(256)
__global__ void attn_scores(const float* __restrict__ qkv, float* __restrict__ S)
{
    int bh = blockIdx.x;
    int b = bh / NHEAD, h = bh - b*NHEAD;
    extern __shared__ float sm[];
    float* qs = sm;               // [198][64]
    float* ks = sm + NSEQ*64;     // [198][65]  (padded)
    int tid = threadIdx.x;
    const float* base = qkv + (size_t)b*NSEQ*(3*CDIM) + h*HD;
    for (int i = tid; i < NSEQ*64; i += 256) {
        int t = i >> 6, d = i & 63;
        const float* rp = base + (size_t)t*(3*CDIM) + d;
        qs[t*64+d] = rp[0];
        ks[t*65+d] = rp[CDIM];
    }
    __syncthreads();
    float* out = S + (size_t)bh*(NSEQ*NSEQ);
    for (int idx = tid; idx < NSEQ*NSEQ; idx += 256) {
        int q = idx / NSEQ, kk = idx - q*NSEQ;
        const float* qp = qs + q*64;
        const float* kp = ks + kk*65;
        float a = 0.f;
#pragma unroll
        for (int d2=0; d2<64; d2++) a = fmaf(qp[d2], kp[d2], a);
        out[idx] = a * 0.125f;   // HD^-0.5
    }
}

// ---------------- mask: sigmoid(mean_h S[b,h,last,:]) ----------------
__global__ void mask_kernel(const float* __restrict__ S, float* __restrict__ mask)
{
    int i = blockIdx.x*256 + threadIdx.x;
    if (i >= NB*NSEQ) return;
    int b = i / NSEQ, kk = i - b*NSEQ;
    float s = 0.f;
    for (int h=0; h<NHEAD; h++)
        s += S[((size_t)(b*NHEAD+h)*NSEQ + 197)*NSEQ + kk];
    s *= (1.f/12.f);
    mask[i] = 1.f/(1.f + expf(-s));
}

// ---------------- softmax (warp per row), optional post-mask multiply ----------------
__launch_bounds__(256)
__global__ void softmax_kernel(float* __restrict__ S, const float* __restrict__ mask, int use_mask)
{
    int gw = (blockIdx.x*256 + threadIdx.x) >> 5;
    int lane = threadIdx.x & 31;
    if (gw >= NB*NHEAD*NSEQ) return;
    float* row = S + (size_t)gw * NSEQ;
    float v[7];
    float mx = -1e30f;
#pragma unroll
    for (int j=0;j<7;j++){
        int kk = lane + 32*j;
        v[j] = (kk < NSEQ) ? row[kk] : -1e30f;
        mx = fmaxf(mx, v[j]);
    }
#pragma unroll
    for (int o=16;o;o>>=1) mx = fmaxf(mx, __shfl_xor_sync(0xffffffffu, mx, o));
    float sum = 0.f;
#pragma unroll
    for (int j=0;j<7;j++){
        int kk = lane + 32*j;
        v[j] = (kk < NSEQ) ? expf(v[j]-mx) : 0.f;
        sum += v[j];
    }
#pragma unroll
    for (int o=16;o;o>>=1) sum += __shfl_xor_sync(0xffffffffu, sum, o);
    float inv = 1.f/sum;
    int b = gw / (NHEAD*NSEQ);
    const float* mrow = mask + (size_t)b*NSEQ;
#pragma unroll
    for (int j=0;j<7;j++){
        int kk = lane + 32*j;
        if (kk < NSEQ) {
            float o2 = v[j]*inv;
            if (use_mask) o2 *= mrow[kk];
            row[kk] = o2;
        }
    }
}

// ---------------- O = P @ V, per (b,h), writes straight into (tok, h*64+d) layout ----------------
#define SMEM_AV ((NSEQ*64 + 32*NSEQ)*4)
__launch_bounds__(256)
__global__ void attn_v(const float* __restrict__ S, const float* __restrict__ qkv, float* __restrict__ O)
{
    int bh = blockIdx.x;
    int b = bh / NHEAD, h = bh - b*NHEAD;
    extern __shared__ float sm[];
    float* vs = sm;             // [198][64]
    float* ps = sm + NSEQ*64;   // [32][198]
    int tid = threadIdx.x;
    const float* vbase = qkv + (size_t)b*NSEQ*(3*CDIM) + 2*CDIM + h*HD;
    for (int i = tid; i < NSEQ*64; i += 256) {
        int t = i >> 6, d = i & 63;
        vs[i] = vbase[(size_t)t*(3*CDIM) + d];
    }
    const float* Sb = S + (size_t)bh*(NSEQ*NSEQ);
    float* Ob = O + (size_t)b*NSEQ*CDIM + h*HD;
    int d = tid & 63, qg = tid >> 6;   // qg: 0..3
    for (int q0 = 0; q0 < NSEQ; q0 += 32) {
        int rows = NSEQ - q0; if (rows > 32) rows = 32;
        __syncthreads();
        for (int i = tid; i < rows*NSEQ; i += 256) ps[i] = Sb[(size_t)q0*NSEQ + i];
        __syncthreads();
        for (int ql = qg; ql < rows; ql += 8) {
            int q2l = ql + 4;
            if (q2l < rows) {
                float a1=0.f, a2=0.f;
                const float* p1 = ps + ql*NSEQ;
                const float* p2 = ps + q2l*NSEQ;
                for (int kk=0; kk<NSEQ; kk++) {
                    float vv = vs[kk*64+d];
                    a1 = fmaf(p1[kk], vv, a1);
                    a2 = fmaf(p2[kk], vv, a2);
                }
                Ob[(size_t)(q0+ql)*CDIM + d]  = a1;
                Ob[(size_t)(q0+q2l)*CDIM + d] = a2;
            } else {
                float a1=0.f;
                const float* p1 = ps + ql*NSEQ;
                for (int kk=0; kk<NSEQ; kk++) a1 = fmaf(p1[kk], vs[kk*64+d], a1);
                Ob[(size_t)(q0+ql)*CDIM + d] = a1;
            }
        }
    }
}

// ---------------- head features: 9 rectangle sums per (b,c)  ----------------
// conv3x3(pad1) then spatial-mean == (1/196) * sum_{c,dy,dx} w[cls,c,dy,dx]*S[b,c,dy,dx]
__launch_bounds__(256)
__global__ void sfeat_kernel(const float* __restrict__ T, float* __restrict__ SF)
{
    int i = blockIdx.x*256 + threadIdx.x;
    if (i >= NB*CDIM) return;
    int b = i / CDIM, c = i - b*CDIM;
    const float* base = T + ((size_t)b*NSEQ + 1)*CDIM + c;
    float tot=0.f, r0=0.f, r13=0.f, c0s=0.f, c13s=0.f;
    for (int u=0; u<14; u++) {
        for (int v=0; v<14; v++) {
            float val = base[(size_t)(u*14+v)*CDIM];
            tot += val;
            if (u==0)  r0  += val;
            if (u==13) r13 += val;
            if (v==0)  c0s += val;
            if (v==13) c13s += val;
        }
    }
    float x00 = base[0];
    float x0e = base[(size_t)13*CDIM];                // xp[0][13]
    float xe0 = base[(size_t)(13*14)*CDIM];           // xp[13][0]
    float xee = base[(size_t)(13*14+13)*CDIM];        // xp[13][13]
    float* o = SF + (size_t)b*6912 + c*9;
    for (int dy=0; dy<3; dy++)
        for (int dx=0; dx<3; dx++) {
            float s = tot;
            if (dy==0) s -= r13;
            if (dy==2) s -= r0;
            if (dx==0) s -= c13s;
            if (dx==2) s -= c0s;
            if (dy==0 && dx==0) s += xee;
            if (dy==0 && dx==2) s += xe0;
            if (dy==2 && dx==0) s += x0e;
            if (dy==2 && dx==2) s += x00;
            o[dy*3+dx] = s;
        }
}

// ---------------- logits: warp per (b,cls), K=6912 dot ----------------
__launch_bounds__(256)
__global__ void head_kernel(const float* __restrict__ SF, const float* __restrict__ W,
                            const float* __restrict__ bias, float* __restrict__ out)
{
    int gw = (blockIdx.x*256 + threadIdx.x) >> 5;
    int lane = threadIdx.x & 31;
    if (gw >= NB*200) return;
    int b = gw / 200, cls = gw - b*200;
    const float* a = SF + (size_t)b*6912;
    const float* w = W + (size_t)cls*6912;
    float s = 0.f;
    for (int k = lane; k < 6912; k += 32) s = fmaf(a[k], w[k], s);
#pragma unroll
    for (int o=16;o;o>>=1) s += __shfl_xor_sync(0xffffffffu, s, o);
    if (lane==0) out[gw] = s*(1.f/196.f) + bias[cls];
}

// ---------------- final mask outputs (per batch) ----------------
__launch_bounds__(256)
__global__ void final_mask(const float* __restrict__ Mlayers, const float* __restrict__ gk,
                           float* __restrict__ out)
{
    int b = blockIdx.x;
    __shared__ float ma[196];
    __shared__ float red[8];
    int tid = threadIdx.x;
    if (tid < 196) {
        float s = 0.f;
        for (int l=9; l<12; l++) s += Mlayers[((size_t)l*NB + b)*NSEQ + 1 + tid];
        ma[tid] = s * (1.f/3.f);
    }
    __syncthreads();
    float part = (tid < 196) ? ma[tid] : 0.f;
#pragma unroll
    for (int o=16;o;o>>=1) part += __shfl_xor_sync(0xffffffffu, part, o);
    if ((tid&31)==0) red[tid>>5] = part;
    __syncthreads();
    if (tid==0){ float t=0.f; for(int i=0;i<8;i++) t+=red[i]; out[12800 + b] = t*(1.f/196.f); }
    float t3 = 0.f;
    if (tid < 196) {
        int y = tid/14, x = tid - y*14;
        float m = 0.f;
        for (int dy=0; dy<3; dy++)
            for (int dx=0; dx<3; dx++) {
                int yy = y+dy-1, xx = x+dx-1;
                if (yy>=0 && yy<14 && xx>=0 && xx<14)
                    m += gk[dy*3+dx]*ma[yy*14+xx];
            }
        t3 = (1.f - m)*m;
    }
    __syncthreads();
#pragma unroll
    for (int o=16;o;o>>=1) t3 += __shfl_xor_sync(0xffffffffu, t3, o);
    if ((tid&31)==0) red[tid>>5] = t3;
    __syncthreads();
    if (tid==0){ float t=0.f; for(int i=0;i<8;i++) t+=red[i]; out[12864 + b] = t*(1.f/196.f); }
}

// ---------------- launch ----------------
extern "C" void kernel_launch(void* const* d_in, const int* in_sizes, int n_in,
                              void* d_out, int out_size)
{
    const float* x       = (const float*)d_in[0];
    const float* patch_w = (const float*)d_in[1];
    const float* patch_b = (const float*)d_in[2];
    const float* cls_tok = (const float*)d_in[3];
    const float* loc_tok = (const float*)d_in[4];
    const float* pos_emb = (const float*)d_in[5];
    const float* loc_emb = (const float*)d_in[6];
    const float* ln1_w   = (const float*)d_in[7];
    const float* ln1_b   = (const float*)d_in[8];
    const float* qkv_w   = (const float*)d_in[9];
    const float* proj_w  = (const float*)d_in[10];
    const float* proj_b  = (const float*)d_in[11];
    const float* ln2_w   = (const float*)d_in[12];
    const float* ln2_b   = (const float*)d_in[13];
    const float* fc1_w   = (const float*)d_in[14];
    const float* fc1_b   = (const float*)d_in[15];
    const float* fc2_w   = (const float*)d_in[16];
    const float* fc2_b   = (const float*)d_in[17];
    const float* norm_w  = (const float*)d_in[18];
    const float* norm_b  = (const float*)d_in[19];
    const float* head_w  = (const float*)d_in[20];
    const float* head_b  = (const float*)d_in[21];
    const float* gk      = (const float*)d_in[22];
    float* out = (float*)d_out;

    float *t, *a, *qkvb, *attn, *o, *hbuf, *maskb, *sfeat;
    cudaGetSymbolAddress((void**)&t,     g_t);
    cudaGetSymbolAddress((void**)&a,     g_a);
    cudaGetSymbolAddress((void**)&qkvb,  g_qkv);
    cudaGetSymbolAddress((void**)&attn,  g_attn);
    cudaGetSymbolAddress((void**)&o,     g_o);
    cudaGetSymbolAddress((void**)&hbuf,  g_h);
    cudaGetSymbolAddress((void**)&maskb, g_mask);
    cudaGetSymbolAddress((void**)&sfeat, g_sfeat);

    cudaFuncSetAttribute(attn_scores, cudaFuncAttributeMaxDynamicSharedMemorySize, SMEM_SCORES);
    cudaFuncSetAttribute(attn_v,      cudaFuncAttributeMaxDynamicSharedMemorySize, SMEM_AV);

    // patch embed
    im2col_patch<<<(NPAT*CDIM+255)/256, 256>>>(x, a);
    gemm_nt<EP_BIAS><<<dim3(6,98), 256>>>(a, patch_w, patch_b, nullptr, o, NPAT, CDIM, CDIM);
    assemble_t<<<(NTOK*CDIM+255)/256, 256>>>(o, cls_tok, loc_tok, pos_emb, loc_emb, t);

    for (int d=0; d<12; d++) {
        ln_kernel<<<NTOK, 256>>>(t, ln1_w + d*CDIM, ln1_b + d*CDIM, a);
        gemm_nt<EP_NONE><<<dim3(18,99), 256>>>(a, qkv_w + (size_t)d*3*CDIM*CDIM, nullptr, nullptr,
                                               qkvb, NTOK, 3*CDIM, CDIM);
        attn_scores<<<NB*NHEAD, 256, SMEM_SCORES>>>(qkvb, attn);
        mask_kernel<<<(NB*NSEQ+255)/256, 256>>>(attn, maskb + (size_t)d*NB*NSEQ);
        softmax_kernel<<<(NB*NHEAD*NSEQ*32+255)/256, 256>>>(attn, maskb + (size_t)d*NB*NSEQ, (d>=9)?1:0);
        attn_v<<<NB*NHEAD, 256, SMEM_AV>>>(attn, qkvb, o);
        gemm_nt<EP_BIAS_RES><<<dim3(6,99), 256>>>(o, proj_w + (size_t)d*CDIM*CDIM, proj_b + d*CDIM,
                                                  t, t, NTOK, CDIM, CDIM);
        ln_kernel<<<NTOK, 256>>>(t, ln2_w + d*CDIM, ln2_b + d*CDIM, a);
        gemm_nt<EP_BIAS_GELU><<<dim3(24,99), 256>>>(a, fc1_w + (size_t)d*4*CDIM*CDIM, fc1_b + d*4*CDIM,
                                                    nullptr, hbuf, NTOK, 4*CDIM, CDIM);
        gemm_nt<EP_BIAS_RES><<<dim3(6,99), 256>>>(hbuf, fc2_w + (size_t)d*CDIM*4*CDIM, fc2_b + d*CDIM,
                                                  t, t, NTOK, CDIM, 4*CDIM);
    }

    ln_kernel<<<NTOK, 256>>>(t, norm_w, norm_b, a);
    sfeat_kernel<<<(NB*CDIM+255)/256, 256>>>(a, sfeat);
    head_kernel<<<(NB*200*32+255)/256, 256>>>(sfeat, head_w, head_b, out);
    final_mask<<<NB, 256>>>(maskb, gk, out);
}

// round 2
// speedup vs baseline: 2.3492x; 2.3492x over previous
#include <cuda_runtime.h>
#include <math.h>

// ---------------- problem constants ----------------
#define NB    64
#define NSEQ  198
#define NTOK  (NB*NSEQ)      // 12672
#define NPAT  (NB*196)       // 12544
#define CDIM  768
#define NHEAD 12
#define HD    64

// ---------------- scratch (device globals; no allocs allowed) ----------------
__device__ float g_t   [(size_t)NTOK*CDIM];       // token stream
__device__ float g_a   [(size_t)NTOK*CDIM];       // LN out / im2col
__device__ float g_qkv [(size_t)NTOK*3*CDIM];     // qkv
__device__ float g_attn[(size_t)NB*NHEAD*NSEQ*NSEQ];
__device__ float g_o   [(size_t)NTOK*CDIM];       // attn out / patch gemm out
__device__ float g_h   [(size_t)NTOK*4*CDIM];     // mlp hidden
__device__ float g_mask[(size_t)12*NB*NSEQ];
__device__ float g_sfeat[(size_t)NB*6912];

enum { EP_NONE=0, EP_BIAS=1, EP_BIAS_RES=2, EP_BIAS_GELU=3 };

// ---------------- tf32 helpers ----------------
__device__ __forceinline__ unsigned f2tf(float x){
    unsigned r; asm("cvt.rna.tf32.f32 %0, %1;" : "=r"(r) : "f"(x)); return r;
}
__device__ __forceinline__ void mma_tf32(float c[4], const unsigned a[4], const unsigned b[2]){
    asm volatile("mma.sync.aligned.m16n8k8.row.col.f32.tf32.tf32.f32 "
        "{%0,%1,%2,%3}, {%4,%5,%6,%7}, {%8,%9}, {%0,%1,%2,%3};\n"
        : "+f"(c[0]),"+f"(c[1]),"+f"(c[2]),"+f"(c[3])
        : "r"(a[0]),"r"(a[1]),"r"(a[2]),"r"(a[3]), "r"(b[0]),"r"(b[1]));
}

// ---------------- tensor-core GEMM-NT: C[M,N] = A[M,K] * B[N,K]^T ----------------
// 128x128x16 tile, 8 warps, warp tile 32x64 (2 m-tiles x 8 n-tiles of m16n8k8)
template<int EPI>
__global__ void __launch_bounds__(256,2) gemm_tc(
    const float* __restrict__ A, const float* __restrict__ B,
    const float* __restrict__ bias, const float* __restrict__ res,
    float* __restrict__ C, int M, int N, int K)
{
    __shared__ unsigned As[128][20];
    __shared__ unsigned Bs[128][20];
    const int tid=threadIdx.x, warp=tid>>5, lane=tid&31;
    const int wm=warp>>1, wn=warp&1;        // warp grid 4x2
    const int gid=lane>>2, tg=lane&3;
    const int bm=blockIdx.y*128, bn=blockIdx.x*128;
    const int lrow=tid>>2, lcol=(tid&3)*4;
    const float* Ag = A + (size_t)(bm+lrow)*K + lcol;
    const float* Bg = B + (size_t)(bn+lrow)*K + lcol;
    const bool aok0=(bm+lrow)<M, aok1=(bm+lrow+64)<M;
    const bool bok0=(bn+lrow)<N, bok1=(bn+lrow+64)<N;

    float acc[2][8][4];
#pragma unroll
    for(int i=0;i<2;i++)
#pragma unroll
        for(int j=0;j<8;j++)
#pragma unroll
            for(int q=0;q<4;q++) acc[i][j][q]=0.f;

    for(int k0=0;k0<K;k0+=16){
        float4 av0=make_float4(0,0,0,0), av1=av0, bv0=av0, bv1=av0;
        if(aok0) av0=*(const float4*)(Ag+k0);
        if(aok1) av1=*(const float4*)(Ag+(size_t)64*K+k0);
        if(bok0) bv0=*(const float4*)(Bg+k0);
        if(bok1) bv1=*(const float4*)(Bg+(size_t)64*K+k0);
        __syncthreads();
        {
            uint4 t;
            t.x=f2tf(av0.x);t.y=f2tf(av0.y);t.z=f2tf(av0.z);t.w=f2tf(av0.w);
            *(uint4*)&As[lrow][lcol]=t;
            t.x=f2tf(av1.x);t.y=f2tf(av1.y);t.z=f2tf(av1.z);t.w=f2tf(av1.w);
            *(uint4*)&As[lrow+64][lcol]=t;
            t.x=f2tf(bv0.x);t.y=f2tf(bv0.y);t.z=f2tf(bv0.z);t.w=f2tf(bv0.w);
            *(uint4*)&Bs[lrow][lcol]=t;
            t.x=f2tf(bv1.x);t.y=f2tf(bv1.y);t.z=f2tf(bv1.z);t.w=f2tf(bv1.w);
            *(uint4*)&Bs[lrow+64][lcol]=t;
        }
        __syncthreads();
#pragma unroll
        for(int ks=0;ks<2;ks++){
            const int kk=ks*8+tg;
            unsigned af[2][4], bf[8][2];
#pragma unroll
            for(int i=0;i<2;i++){
                int r=wm*32+i*16+gid;
                af[i][0]=As[r][kk];   af[i][1]=As[r+8][kk];
                af[i][2]=As[r][kk+4]; af[i][3]=As[r+8][kk+4];
            }
#pragma unroll
            for(int j=0;j<8;j++){
                int c=wn*64+j*8+gid;
                bf[j][0]=Bs[c][kk]; bf[j][1]=Bs[c][kk+4];
            }
#pragma unroll
            for(int i=0;i<2;i++)
#pragma unroll
                for(int j=0;j<8;j++)
                    mma_tf32(acc[i][j], af[i], bf[j]);
        }
    }

    // epilogue: c0/c1 at (row, col..col+1), c2/c3 at (row+8, ...)
#pragma unroll
    for(int i=0;i<2;i++){
        int rbase = bm + wm*32 + i*16 + gid;
#pragma unroll
        for(int rr=0;rr<2;rr++){
            int row = rbase + rr*8;
            if(row >= M) continue;
#pragma unroll
            for(int j=0;j<8;j++){
                int col = bn + wn*64 + j*8 + tg*2;
                if(col+1 >= N+1) continue;   // N always mult of 2 here
                float v0 = acc[i][j][rr*2+0];
                float v1 = acc[i][j][rr*2+1];
                if (EPI == EP_BIAS) { v0 += bias[col]; v1 += bias[col+1]; }
                else if (EPI == EP_BIAS_RES) {
                    v0 += bias[col]   + res[(size_t)row*N+col];
                    v1 += bias[col+1] + res[(size_t)row*N+col+1];
                }
                else if (EPI == EP_BIAS_GELU) {
                    v0 += bias[col];   v1 += bias[col+1];
                    v0 = 0.5f*v0*(1.f + erff(v0*0.70710678118654752f));
                    v1 = 0.5f*v1*(1.f + erff(v1*0.70710678118654752f));
                }
                if (col+1 < N) *(float2*)&C[(size_t)row*N+col] = make_float2(v0,v1);
                else if (col < N) C[(size_t)row*N+col] = v0;
            }
        }
    }
}

// ---------------- patch im2col (non-overlapping 16x16 patches) ----------------
__global__ void im2col_patch(const float* __restrict__ x, float* __restrict__ A)
{
    int i = blockIdx.x*256 + threadIdx.x;
    if (i >= NPAT*CDIM) return;
    int p = i / CDIM, kidx = i - p*CDIM;
    int b = p / 196, pp = p - b*196;
    int py = pp / 14, px = pp - py*14;
    int c = kidx >> 8;
    int rem = kidx & 255;
    int iy = rem >> 4, ix = rem & 15;
    A[i] = x[(((size_t)b*3 + c)*224 + (py*16+iy))*224 + (px*16+ix)];
}

// ---------------- assemble token stream: cls | patches | loc, + pos ----------------
__global__ void assemble_t(const float* __restrict__ P, const float* __restrict__ cls,
                           const float* __restrict__ loc, const float* __restrict__ pos,
                           const float* __restrict__ loce, float* __restrict__ T)
{
    int i = blockIdx.x*256 + threadIdx.x;
    if (i >= NTOK*CDIM) return;
    int tok = i / CDIM, c = i - tok*CDIM;
    int b = tok / NSEQ, tt = tok - b*NSEQ;
    float v;
    if (tt == 0)          v = cls[c] + pos[c];
    else if (tt == 197)   v = loc[c] + loce[c];
    else                  v = P[((size_t)b*196 + tt-1)*CDIM + c] + pos[(size_t)tt*CDIM + c];
    T[i] = v;
}

// ---------------- layernorm (block per token row of 768) ----------------
__launch_bounds__(256)
__global__ void ln_kernel(const float* __restrict__ X, const float* __restrict__ w,
                          const float* __restrict__ bb, float* __restrict__ Y)
{
    int row = blockIdx.x;
    const float* x = X + (size_t)row * CDIM;
    float* y = Y + (size_t)row * CDIM;
    int tid = threadIdx.x;
    float v0 = x[tid], v1 = x[tid+256], v2 = x[tid+512];
    __shared__ float red[8];
    __shared__ float mrs[2];
    float s = v0+v1+v2;
#pragma unroll
    for (int o=16;o;o>>=1) s += __shfl_xor_sync(0xffffffffu, s, o);
    if ((tid&31)==0) red[tid>>5] = s;
    __syncthreads();
    if (tid==0){ float t=0.f; for(int i=0;i<8;i++) t+=red[i]; mrs[0]=t*(1.f/768.f); }
    __syncthreads();
    float m = mrs[0];
    float d0=v0-m, d1=v1-m, d2=v2-m;
    float q = d0*d0+d1*d1+d2*d2;
#pragma unroll
    for (int o=16;o;o>>=1) q += __shfl_xor_sync(0xffffffffu, q, o);
    __syncthreads();
    if ((tid&31)==0) red[tid>>5] = q;
    __syncthreads();
    if (tid==0){ float t=0.f; for(int i=0;i<8;i++) t+=red[i]; mrs[1]=rsqrtf(t*(1.f/768.f)+1e-5f); }
    __syncthreads();
    float rs = mrs[1];
    y[tid]     = d0*rs*w[tid]     + bb[tid];
    y[tid+256] = d1*rs*w[tid+256] + bb[tid+256];
    y[tid+512] = d2*rs*w[tid+512] + bb[tid+512];
}

// ---------------- attention scores: S = q k^T * scale, per (b,h) block ----------------
#define SMEM_SCORES ((NSEQ*64 + NSEQ*65)*4)
__launch_bounds__(256)
__global__ void attn_scores(const float* __restrict__ qkv, float* __restrict__ S)
{
    int bh = blockIdx.x;
    int b = bh / NHEAD, h = bh - b*NHEAD;
    extern __shared__ float sm[];
    float* qs = sm;               // [198][64]
    float* ks = sm + NSEQ*64;     // [198][65]  (padded)
    int tid = threadIdx.x;
    const float* base = qkv + (size_t)b*NSEQ*(3*CDIM) + h*HD;
    for (int i = tid; i < NSEQ*64; i += 256) {
        int t = i >> 6, d = i & 63;
        const float* rp = base + (size_t)t*(3*CDIM) + d;
        qs[t*64+d] = rp[0];
        ks[t*65+d] = rp[CDIM];
    }
    __syncthreads();
    float* out = S + (size_t)bh*(NSEQ*NSEQ);
    for (int idx = tid; idx < NSEQ*NSEQ; idx += 256) {
        int q = idx / NSEQ, kk = idx - q*NSEQ;
        const float* qp = qs + q*64;
        const float* kp = ks + kk*65;
        float a = 0.f;
#pragma unroll
        for (int d2=0; d2<64; d2++) a = fmaf(qp[d2], kp[d2], a);
        out[idx] = a * 0.125f;   // HD^-0.5
    }
}

// ---------------- mask: sigmoid(mean_h S[b,h,last,:]) ----------------
__global__ void mask_kernel(const float* __restrict__ S, float* __restrict__ mask)
{
    int i = blockIdx.x*256 + threadIdx.x;
    if (i >= NB*NSEQ) return;
    int b = i / NSEQ, kk = i - b*NSEQ;
    float s = 0.f;
    for (int h=0; h<NHEAD; h++)
        s += S[((size_t)(b*NHEAD+h)*NSEQ + 197)*NSEQ + kk];
    s *= (1.f/12.f);
    mask[i] = 1.f/(1.f + expf(-s));
}

// ---------------- softmax (warp per row), optional post-mask multiply ----------------
__launch_bounds__(256)
__global__ void softmax_kernel(float* __restrict__ S, const float* __restrict__ mask, int use_mask)
{
    int gw = (blockIdx.x*256 + threadIdx.x) >> 5;
    int lane = threadIdx.x & 31;
    if (gw >= NB*NHEAD*NSEQ) return;
    float* row = S + (size_t)gw * NSEQ;
    float v[7];
    float mx = -1e30f;
#pragma unroll
    for (int j=0;j<7;j++){
        int kk = lane + 32*j;
        v[j] = (kk < NSEQ) ? row[kk] : -1e30f;
        mx = fmaxf(mx, v[j]);
    }
#pragma unroll
    for (int o=16;o;o>>=1) mx = fmaxf(mx, __shfl_xor_sync(0xffffffffu, mx, o));
    float sum = 0.f;
#pragma unroll
    for (int j=0;j<7;j++){
        int kk = lane + 32*j;
        v[j] = (kk < NSEQ) ? expf(v[j]-mx) : 0.f;
        sum += v[j];
    }
#pragma unroll
    for (int o=16;o;o>>=1) sum += __shfl_xor_sync(0xffffffffu, sum, o);
    float inv = 1.f/sum;
    int b = gw / (NHEAD*NSEQ);
    const float* mrow = mask + (size_t)b*NSEQ;
#pragma unroll
    for (int j=0;j<7;j++){
        int kk = lane + 32*j;
        if (kk < NSEQ) {
            float o2 = v[j]*inv;
            if (use_mask) o2 *= mrow[kk];
            row[kk] = o2;
        }
    }
}

// ---------------- O = P @ V, per (b,h), writes straight into (tok, h*64+d) layout ----------------
#define SMEM_AV ((NSEQ*64 + 32*NSEQ)*4)
__launch_bounds__(256)
__global__ void attn_v(const float* __restrict__ S, const float* __restrict__ qkv, float* __restrict__ O)
{
    int bh = blockIdx.x;
    int b = bh / NHEAD, h = bh - b*NHEAD;
    extern __shared__ float sm[];
    float* vs = sm;             // [198][64]
    float* ps = sm + NSEQ*64;   // [32][198]
    int tid = threadIdx.x;
    const float* vbase = qkv + (size_t)b*NSEQ*(3*CDIM) + 2*CDIM + h*HD;
    for (int i = tid; i < NSEQ*64; i += 256) {
        int t = i >> 6, d = i & 63;
        vs[i] = vbase[(size_t)t*(3*CDIM) + d];
    }
    const float* Sb = S + (size_t)bh*(NSEQ*NSEQ);
    float* Ob = O + (size_t)b*NSEQ*CDIM + h*HD;
    int d = tid & 63, qg = tid >> 6;   // qg: 0..3
    for (int q0 = 0; q0 < NSEQ; q0 += 32) {
        int rows = NSEQ - q0; if (rows > 32) rows = 32;
        __syncthreads();
        for (int i = tid; i < rows*NSEQ; i += 256) ps[i] = Sb[(size_t)q0*NSEQ + i];
        __syncthreads();
        for (int ql = qg; ql < rows; ql += 8) {
            int q2l = ql + 4;
            if (q2l < rows) {
                float a1=0.f, a2=0.f;
                const float* p1 = ps + ql*NSEQ;
                const float* p2 = ps + q2l*NSEQ;
                for (int kk=0; kk<NSEQ; kk++) {
                    float vv = vs[kk*64+d];
                    a1 = fmaf(p1[kk], vv, a1);
                    a2 = fmaf(p2[kk], vv, a2);
                }
                Ob[(size_t)(q0+ql)*CDIM + d]  = a1;
                Ob[(size_t)(q0+q2l)*CDIM + d] = a2;
            } else {
                float a1=0.f;
                const float* p1 = ps + ql*NSEQ;
                for (int kk=0; kk<NSEQ; kk++) a1 = fmaf(p1[kk], vs[kk*64+d], a1);
                Ob[(size_t)(q0+ql)*CDIM + d] = a1;
            }
        }
    }
}

// ---------------- head features: 9 rectangle sums per (b,c)  ----------------
__launch_bounds__(256)
__global__ void sfeat_kernel(const float* __restrict__ T, float* __restrict__ SF)
{
    int i = blockIdx.x*256 + threadIdx.x;
    if (i >= NB*CDIM) return;
    int b = i / CDIM, c = i - b*CDIM;
    const float* base = T + ((size_t)b*NSEQ + 1)*CDIM + c;
    float tot=0.f, r0=0.f, r13=0.f, c0s=0.f, c13s=0.f;
    for (int u=0; u<14; u++) {
        for (int v=0; v<14; v++) {
            float val = base[(size_t)(u*14+v)*CDIM];
            tot += val;
            if (u==0)  r0  += val;
            if (u==13) r13 += val;
            if (v==0)  c0s += val;
            if (v==13) c13s += val;
        }
    }
    float x00 = base[0];
    float x0e = base[(size_t)13*CDIM];
    float xe0 = base[(size_t)(13*14)*CDIM];
    float xee = base[(size_t)(13*14+13)*CDIM];
    float* o = SF + (size_t)b*6912 + c*9;
    for (int dy=0; dy<3; dy++)
        for (int dx=0; dx<3; dx++) {
            float s = tot;
            if (dy==0) s -= r13;
            if (dy==2) s -= r0;
            if (dx==0) s -= c13s;
            if (dx==2) s -= c0s;
            if (dy==0 && dx==0) s += xee;
            if (dy==0 && dx==2) s += xe0;
            if (dy==2 && dx==0) s += x0e;
            if (dy==2 && dx==2) s += x00;
            o[dy*3+dx] = s;
        }
}

// ---------------- logits: warp per (b,cls), K=6912 dot ----------------
__launch_bounds__(256)
__global__ void head_kernel(const float* __restrict__ SF, const float* __restrict__ W,
                            const float* __restrict__ bias, float* __restrict__ out)
{
    int gw = (blockIdx.x*256 + threadIdx.x) >> 5;
    int lane = threadIdx.x & 31;
    if (gw >= NB*200) return;
    int b = gw / 200, cls = gw - b*200;
    const float* a = SF + (size_t)b*6912;
    const float* w = W + (size_t)cls*6912;
    float s = 0.f;
    for (int k = lane; k < 6912; k += 32) s = fmaf(a[k], w[k], s);
#pragma unroll
    for (int o=16;o;o>>=1) s += __shfl_xor_sync(0xffffffffu, s, o);
    if (lane==0) out[gw] = s*(1.f/196.f) + bias[cls];
}

// ---------------- final mask outputs (per batch) ----------------
__launch_bounds__(256)
__global__ void final_mask(const float* __restrict__ Mlayers, const float* __restrict__ gk,
                           float* __restrict__ out)
{
    int b = blockIdx.x;
    __shared__ float ma[196];
    __shared__ float red[8];
    int tid = threadIdx.x;
    if (tid < 196) {
        float s = 0.f;
        for (int l=9; l<12; l++) s += Mlayers[((size_t)l*NB + b)*NSEQ + 1 + tid];
        ma[tid] = s * (1.f/3.f);
    }
    __syncthreads();
    float part = (tid < 196) ? ma[tid] : 0.f;
#pragma unroll
    for (int o=16;o;o>>=1) part += __shfl_xor_sync(0xffffffffu, part, o);
    if ((tid&31)==0) red[tid>>5] = part;
    __syncthreads();
    if (tid==0){ float t=0.f; for(int i=0;i<8;i++) t+=red[i]; out[12800 + b] = t*(1.f/196.f); }
    float t3 = 0.f;
    if (tid < 196) {
        int y = tid/14, x = tid - y*14;
        float m = 0.f;
        for (int dy=0; dy<3; dy++)
            for (int dx=0; dx<3; dx++) {
                int yy = y+dy-1, xx = x+dx-1;
                if (yy>=0 && yy<14 && xx>=0 && xx<14)
                    m += gk[dy*3+dx]*ma[yy*14+xx];
            }
        t3 = (1.f - m)*m;
    }
    __syncthreads();
#pragma unroll
    for (int o=16;o;o>>=1) t3 += __shfl_xor_sync(0xffffffffu, t3, o);
    if ((tid&31)==0) red[tid>>5] = t3;
    __syncthreads();
    if (tid==0){ float t=0.f; for(int i=0;i<8;i++) t+=red[i]; out[12864 + b] = t*(1.f/196.f); }
}

// ---------------- launch ----------------
extern "C" void kernel_launch(void* const* d_in, const int* in_sizes, int n_in,
                              void* d_out, int out_size)
{
    const float* x       = (const float*)d_in[0];
    const float* patch_w = (const float*)d_in[1];
    const float* patch_b = (const float*)d_in[2];
    const float* cls_tok = (const float*)d_in[3];
    const float* loc_tok = (const float*)d_in[4];
    const float* pos_emb = (const float*)d_in[5];
    const float* loc_emb = (const float*)d_in[6];
    const float* ln1_w   = (const float*)d_in[7];
    const float* ln1_b   = (const float*)d_in[8];
    const float* qkv_w   = (const float*)d_in[9];
    const float* proj_w  = (const float*)d_in[10];
    const float* proj_b  = (const float*)d_in[11];
    const float* ln2_w   = (const float*)d_in[12];
    const float* ln2_b   = (const float*)d_in[13];
    const float* fc1_w   = (const float*)d_in[14];
    const float* fc1_b   = (const float*)d_in[15];
    const float* fc2_w   = (const float*)d_in[16];
    const float* fc2_b   = (const float*)d_in[17];
    const float* norm_w  = (const float*)d_in[18];
    const float* norm_b  = (const float*)d_in[19];
    const float* head_w  = (const float*)d_in[20];
    const float* head_b  = (const float*)d_in[21];
    const float* gk      = (const float*)d_in[22];
    float* out = (float*)d_out;

    float *t, *a, *qkvb, *attn, *o, *hbuf, *maskb, *sfeat;
    cudaGetSymbolAddress((void**)&t,     g_t);
    cudaGetSymbolAddress((void**)&a,     g_a);
    cudaGetSymbolAddress((void**)&qkvb,  g_qkv);
    cudaGetSymbolAddress((void**)&attn,  g_attn);
    cudaGetSymbolAddress((void**)&o,     g_o);
    cudaGetSymbolAddress((void**)&hbuf,  g_h);
    cudaGetSymbolAddress((void**)&maskb, g_mask);
    cudaGetSymbolAddress((void**)&sfeat, g_sfeat);

    cudaFuncSetAttribute(attn_scores, cudaFuncAttributeMaxDynamicSharedMemorySize, SMEM_SCORES);
    cudaFuncSetAttribute(attn_v,      cudaFuncAttributeMaxDynamicSharedMemorySize, SMEM_AV);

    // patch embed
    im2col_patch<<<(NPAT*CDIM+255)/256, 256>>>(x, a);
    gemm_tc<EP_BIAS><<<dim3(6,98), 256>>>(a, patch_w, patch_b, nullptr, o, NPAT, CDIM, CDIM);
    assemble_t<<<(NTOK*CDIM+255)/256, 256>>>(o, cls_tok, loc_tok, pos_emb, loc_emb, t);

    for (int d=0; d<12; d++) {
        ln_kernel<<<NTOK, 256>>>(t, ln1_w + d*CDIM, ln1_b + d*CDIM, a);
        gemm_tc<EP_NONE><<<dim3(18,99), 256>>>(a, qkv_w + (size_t)d*3*CDIM*CDIM, nullptr, nullptr,
                                               qkvb, NTOK, 3*CDIM, CDIM);
        attn_scores<<<NB*NHEAD, 256, SMEM_SCORES>>>(qkvb, attn);
        mask_kernel<<<(NB*NSEQ+255)/256, 256>>>(attn, maskb + (size_t)d*NB*NSEQ);
        softmax_kernel<<<(NB*NHEAD*NSEQ*32+255)/256, 256>>>(attn, maskb + (size_t)d*NB*NSEQ, (d>=9)?1:0);
        attn_v<<<NB*NHEAD, 256, SMEM_AV>>>(attn, qkvb, o);
        gemm_tc<EP_BIAS_RES><<<dim3(6,99), 256>>>(o, proj_w + (size_t)d*CDIM*CDIM, proj_b + d*CDIM,
                                                  t, t, NTOK, CDIM, CDIM);
        ln_kernel<<<NTOK, 256>>>(t, ln2_w + d*CDIM, ln2_b + d*CDIM, a);
        gemm_tc<EP_BIAS_GELU><<<dim3(24,99), 256>>>(a, fc1_w + (size_t)d*4*CDIM*CDIM, fc1_b + d*4*CDIM,
                                                    nullptr, hbuf, NTOK, 4*CDIM, CDIM);
        gemm_tc<EP_BIAS_RES><<<dim3(6,99), 256>>>(hbuf, fc2_w + (size_t)d*CDIM*4*CDIM, fc2_b + d*CDIM,
                                                  t, t, NTOK, CDIM, 4*CDIM);
    }

    ln_kernel<<<NTOK, 256>>>(t, norm_w, norm_b, a);
    sfeat_kernel<<<(NB*CDIM+255)/256, 256>>>(a, sfeat);
    head_kernel<<<(NB*200*32+255)/256, 256>>>(sfeat, head_w, head_b, out);
    final_mask<<<NB, 256>>>(maskb, gk, out);
}

// round 3
// speedup vs baseline: 3.7600x; 1.6005x over previous
#include <cuda_runtime.h>
#include <cuda_fp16.h>
#include <math.h>

// ---------------- problem constants ----------------
#define NB    64
#define NSEQ  198
#define NTOK  (NB*NSEQ)      // 12672 = 99*128
#define NPAT  (NB*196)       // 12544 = 98*128
#define CDIM  768
#define NHEAD 12
#define HD    64

// ---------------- scratch (device globals; no allocs allowed) ----------------
__device__ float g_t   [(size_t)NTOK*CDIM];
__device__ float g_a   [(size_t)NTOK*CDIM];
__device__ float g_qkv [(size_t)NTOK*3*CDIM];
__device__ float g_attn[(size_t)NB*NHEAD*NSEQ*NSEQ];
__device__ float g_o   [(size_t)NTOK*CDIM];
__device__ float g_h   [(size_t)NTOK*4*CDIM];
__device__ float g_mask[(size_t)12*NB*NSEQ];
__device__ float g_sfeat[(size_t)NB*6912];

enum { EP_NONE=0, EP_BIAS=1, EP_BIAS_RES=2, EP_BIAS_GELU=3 };

// ---------------- fp16 mma helper ----------------
__device__ __forceinline__ void mma_fp16(float c[4], const unsigned a[4], const unsigned b[2]){
    asm volatile("mma.sync.aligned.m16n8k16.row.col.f32.f16.f16.f32 "
        "{%0,%1,%2,%3}, {%4,%5,%6,%7}, {%8,%9}, {%0,%1,%2,%3};\n"
        : "+f"(c[0]),"+f"(c[1]),"+f"(c[2]),"+f"(c[3])
        : "r"(a[0]),"r"(a[1]),"r"(a[2]),"r"(a[3]), "r"(b[0]),"r"(b[1]));
}

// ---------------- fp16 GEMM-NT: C[M,N] = A[M,K]*B[N,K]^T ----------------
// 128x128x32 tile, 8 warps (warp tile 32x64), double-buffered smem,
// all dims guaranteed multiples of tile sizes -> no bounds checks.
template<int EPI>
__global__ void __launch_bounds__(256) gemm_fp16(
    const float* __restrict__ A, const float* __restrict__ B,
    const float* __restrict__ bias, const float* __restrict__ res,
    float* __restrict__ C, int M, int N, int K)
{
    __shared__ __half As[2][128][40];
    __shared__ __half Bs[2][128][40];
    const int tid=threadIdx.x, warp=tid>>5, lane=tid&31;
    const int wm=warp>>1, wn=warp&1;
    const int gid=lane>>2, tg=lane&3;
    const int bm=blockIdx.y*128, bn=blockIdx.x*128;
    const int r0 = tid>>3, c4 = tid&7;

    const float* Agp = A + (size_t)(bm + r0)*K + c4*4;
    const float* Bgp = B + (size_t)(bn + r0)*K + c4*4;

    float acc[2][8][4];
#pragma unroll
    for(int i=0;i<2;i++)
#pragma unroll
        for(int j=0;j<8;j++)
#pragma unroll
            for(int q=0;q<4;q++) acc[i][j][q]=0.f;

    float4 ra[4], rb[4];
#pragma unroll
    for(int i=0;i<4;i++){
        ra[i]=*(const float4*)(Agp + (size_t)(32*i)*K);
        rb[i]=*(const float4*)(Bgp + (size_t)(32*i)*K);
    }

    const int nit = K >> 5;
    // store tile 0
#pragma unroll
    for(int i=0;i<4;i++){
        __half2 a0=__floats2half2_rn(ra[i].x,ra[i].y), a1=__floats2half2_rn(ra[i].z,ra[i].w);
        __half2 b0=__floats2half2_rn(rb[i].x,rb[i].y), b1=__floats2half2_rn(rb[i].z,rb[i].w);
        uint2 ua; ua.x=*(unsigned*)&a0; ua.y=*(unsigned*)&a1;
        uint2 ub; ub.x=*(unsigned*)&b0; ub.y=*(unsigned*)&b1;
        *(uint2*)&As[0][r0+32*i][c4*4] = ua;
        *(uint2*)&Bs[0][r0+32*i][c4*4] = ub;
    }
    __syncthreads();

    for(int it=0; it<nit; it++){
        const int cur = it&1;
        if (it+1 < nit){
            const size_t off = (size_t)(it+1)*32;
#pragma unroll
            for(int i=0;i<4;i++){
                ra[i]=*(const float4*)(Agp + (size_t)(32*i)*K + off);
                rb[i]=*(const float4*)(Bgp + (size_t)(32*i)*K + off);
            }
        }
#pragma unroll
        for(int ks=0; ks<2; ks++){
            const int kb = ks*16 + 2*tg;
            unsigned af[2][4], bf[8][2];
#pragma unroll
            for(int i=0;i<2;i++){
                int r = wm*32 + i*16 + gid;
                af[i][0]=*(const unsigned*)&As[cur][r  ][kb];
                af[i][1]=*(const unsigned*)&As[cur][r+8][kb];
                af[i][2]=*(const unsigned*)&As[cur][r  ][kb+8];
                af[i][3]=*(const unsigned*)&As[cur][r+8][kb+8];
            }
#pragma unroll
            for(int j=0;j<8;j++){
                int c = wn*64 + j*8 + gid;
                bf[j][0]=*(const unsigned*)&Bs[cur][c][kb];
                bf[j][1]=*(const unsigned*)&Bs[cur][c][kb+8];
            }
#pragma unroll
            for(int i=0;i<2;i++)
#pragma unroll
                for(int j=0;j<8;j++)
                    mma_fp16(acc[i][j], af[i], bf[j]);
        }
        if (it+1 < nit){
            const int nxt = cur^1;
#pragma unroll
            for(int i=0;i<4;i++){
                __half2 a0=__floats2half2_rn(ra[i].x,ra[i].y), a1=__floats2half2_rn(ra[i].z,ra[i].w);
                __half2 b0=__floats2half2_rn(rb[i].x,rb[i].y), b1=__floats2half2_rn(rb[i].z,rb[i].w);
                uint2 ua; ua.x=*(unsigned*)&a0; ua.y=*(unsigned*)&a1;
                uint2 ub; ub.x=*(unsigned*)&b0; ub.y=*(unsigned*)&b1;
                *(uint2*)&As[nxt][r0+32*i][c4*4] = ua;
                *(uint2*)&Bs[nxt][r0+32*i][c4*4] = ub;
            }
        }
        __syncthreads();
    }

#pragma unroll
    for(int i=0;i<2;i++){
#pragma unroll
        for(int rr=0;rr<2;rr++){
            int row = bm + wm*32 + i*16 + gid + rr*8;
#pragma unroll
            for(int j=0;j<8;j++){
                int col = bn + wn*64 + j*8 + tg*2;
                float v0 = acc[i][j][rr*2+0];
                float v1 = acc[i][j][rr*2+1];
                if (EPI == EP_BIAS) { v0 += bias[col]; v1 += bias[col+1]; }
                else if (EPI == EP_BIAS_RES) {
                    v0 += bias[col]   + res[(size_t)row*N+col];
                    v1 += bias[col+1] + res[(size_t)row*N+col+1];
                }
                else if (EPI == EP_BIAS_GELU) {
                    v0 += bias[col];   v1 += bias[col+1];
                    v0 = 0.5f*v0*(1.f + erff(v0*0.70710678118654752f));
                    v1 = 0.5f*v1*(1.f + erff(v1*0.70710678118654752f));
                }
                *(float2*)&C[(size_t)row*N+col] = make_float2(v0,v1);
            }
        }
    }
}

// ---------------- patch im2col ----------------
__global__ void im2col_patch(const float* __restrict__ x, float* __restrict__ A)
{
    int i = blockIdx.x*256 + threadIdx.x;
    if (i >= NPAT*CDIM) return;
    int p = i / CDIM, kidx = i - p*CDIM;
    int b = p / 196, pp = p - b*196;
    int py = pp / 14, px = pp - py*14;
    int c = kidx >> 8;
    int rem = kidx & 255;
    int iy = rem >> 4, ix = rem & 15;
    A[i] = x[(((size_t)b*3 + c)*224 + (py*16+iy))*224 + (px*16+ix)];
}

// ---------------- assemble token stream ----------------
__global__ void assemble_t(const float* __restrict__ P, const float* __restrict__ cls,
                           const float* __restrict__ loc, const float* __restrict__ pos,
                           const float* __restrict__ loce, float* __restrict__ T)
{
    int i = blockIdx.x*256 + threadIdx.x;
    if (i >= NTOK*CDIM) return;
    int tok = i / CDIM, c = i - tok*CDIM;
    int b = tok / NSEQ, tt = tok - b*NSEQ;
    float v;
    if (tt == 0)          v = cls[c] + pos[c];
    else if (tt == 197)   v = loc[c] + loce[c];
    else                  v = P[((size_t)b*196 + tt-1)*CDIM + c] + pos[(size_t)tt*CDIM + c];
    T[i] = v;
}

// ---------------- layernorm ----------------
__launch_bounds__(256)
__global__ void ln_kernel(const float* __restrict__ X, const float* __restrict__ w,
                          const float* __restrict__ bb, float* __restrict__ Y)
{
    int row = blockIdx.x;
    const float* x = X + (size_t)row * CDIM;
    float* y = Y + (size_t)row * CDIM;
    int tid = threadIdx.x;
    float v0 = x[tid], v1 = x[tid+256], v2 = x[tid+512];
    __shared__ float red[8];
    __shared__ float mrs[2];
    float s = v0+v1+v2;
#pragma unroll
    for (int o=16;o;o>>=1) s += __shfl_xor_sync(0xffffffffu, s, o);
    if ((tid&31)==0) red[tid>>5] = s;
    __syncthreads();
    if (tid==0){ float t=0.f; for(int i=0;i<8;i++) t+=red[i]; mrs[0]=t*(1.f/768.f); }
    __syncthreads();
    float m = mrs[0];
    float d0=v0-m, d1=v1-m, d2=v2-m;
    float q = d0*d0+d1*d1+d2*d2;
#pragma unroll
    for (int o=16;o;o>>=1) q += __shfl_xor_sync(0xffffffffu, q, o);
    __syncthreads();
    if ((tid&31)==0) red[tid>>5] = q;
    __syncthreads();
    if (tid==0){ float t=0.f; for(int i=0;i<8;i++) t+=red[i]; mrs[1]=rsqrtf(t*(1.f/768.f)+1e-5f); }
    __syncthreads();
    float rs = mrs[1];
    y[tid]     = d0*rs*w[tid]     + bb[tid];
    y[tid+256] = d1*rs*w[tid+256] + bb[tid+256];
    y[tid+512] = d2*rs*w[tid+512] + bb[tid+512];
}

// ---------------- mask precompute: sigmoid(mean_h q197.k / 8) ----------------
// mean over heads of per-head dots == one 768-wide dot (heads contiguous)
__launch_bounds__(256)
__global__ void mask_pre(const float* __restrict__ qkv, float* __restrict__ mask)
{
    int b = blockIdx.x;
    __shared__ float q197[CDIM];
    int tid = threadIdx.x;
    const float* qrow = qkv + ((size_t)b*NSEQ + 197)*(3*CDIM);
    for (int i=tid;i<CDIM;i+=256) q197[i]=qrow[i];
    __syncthreads();
    int warp=tid>>5, lane=tid&31;
    for (int k=warp; k<NSEQ; k+=8){
        const float* krow = qkv + ((size_t)b*NSEQ + k)*(3*CDIM) + CDIM;
        float s=0.f;
        for (int d=lane; d<CDIM; d+=32) s = fmaf(q197[d], krow[d], s);
#pragma unroll
        for (int o=16;o;o>>=1) s += __shfl_xor_sync(0xffffffffu, s, o);
        if (lane==0) mask[(size_t)b*NSEQ + k] = 1.f/(1.f + __expf(-s*(0.125f/12.f)));
    }
}

// ---------------- fused scores + softmax (+mask) ----------------
#define SMEM_SCORES ((NSEQ*64 + NSEQ*65)*4)
__launch_bounds__(256)
__global__ void attn_fused(const float* __restrict__ qkv, float* __restrict__ S,
                           const float* __restrict__ mask, int use_mask)
{
    int bh = blockIdx.x;
    int b = bh / NHEAD, h = bh - b*NHEAD;
    extern __shared__ float sm[];
    float* qs = sm;               // [198][64]
    float* ks = sm + NSEQ*64;     // [198][65] padded
    int tid = threadIdx.x;
    const float* base = qkv + (size_t)b*NSEQ*(3*CDIM) + h*HD;
    for (int i = tid; i < NSEQ*64; i += 256) {
        int t = i >> 6, d = i & 63;
        const float* rp = base + (size_t)t*(3*CDIM) + d;
        qs[t*64+d] = rp[0];
        ks[t*65+d] = rp[CDIM];
    }
    __syncthreads();
    int warp = tid>>5, lane = tid&31;
    float* out = S + (size_t)bh*(NSEQ*NSEQ);
    const float* mrow = mask + (size_t)b*NSEQ;

    const float* kp[7];
    bool valid[7];
#pragma unroll
    for (int j=0;j<7;j++){
        int kk = lane + 32*j;
        valid[j] = kk < NSEQ;
        kp[j] = ks + (valid[j] ? kk : 0)*65;
    }

    for (int q0 = warp*2; q0 < NSEQ; q0 += 16){
        const float* qp0 = qs + q0*64;
        const float* qp1 = qs + (q0+1)*64;
        float va[7], vb[7];
#pragma unroll
        for (int j=0;j<7;j++){ va[j]=0.f; vb[j]=0.f; }
        for (int d=0; d<64; d++){
            float qa = qp0[d], qb = qp1[d];
#pragma unroll
            for (int j=0;j<7;j++){
                float kv = kp[j][d];
                va[j] = fmaf(qa, kv, va[j]);
                vb[j] = fmaf(qb, kv, vb[j]);
            }
        }
        float mxa=-1e30f, mxb=-1e30f;
#pragma unroll
        for (int j=0;j<7;j++){
            va[j] = valid[j] ? va[j]*0.125f : -1e30f;
            vb[j] = valid[j] ? vb[j]*0.125f : -1e30f;
            mxa = fmaxf(mxa, va[j]); mxb = fmaxf(mxb, vb[j]);
        }
#pragma unroll
        for (int o=16;o;o>>=1){
            mxa = fmaxf(mxa, __shfl_xor_sync(0xffffffffu, mxa, o));
            mxb = fmaxf(mxb, __shfl_xor_sync(0xffffffffu, mxb, o));
        }
        float sa=0.f, sb=0.f;
#pragma unroll
        for (int j=0;j<7;j++){
            va[j] = valid[j] ? __expf(va[j]-mxa) : 0.f;
            vb[j] = valid[j] ? __expf(vb[j]-mxb) : 0.f;
            sa += va[j]; sb += vb[j];
        }
#pragma unroll
        for (int o=16;o;o>>=1){
            sa += __shfl_xor_sync(0xffffffffu, sa, o);
            sb += __shfl_xor_sync(0xffffffffu, sb, o);
        }
        float ia = 1.f/sa, ib = 1.f/sb;
        float* o0 = out + (size_t)q0*NSEQ;
        float* o1 = o0 + NSEQ;
#pragma unroll
        for (int j=0;j<7;j++){
            int kk = lane + 32*j;
            if (kk < NSEQ){
                float f = use_mask ? mrow[kk] : 1.f;
                o0[kk] = va[j]*ia*f;
                o1[kk] = vb[j]*ib*f;
            }
        }
    }
}

// ---------------- O = P @ V ----------------
#define SMEM_AV ((NSEQ*64 + 32*NSEQ)*4)
__launch_bounds__(256)
__global__ void attn_v(const float* __restrict__ S, const float* __restrict__ qkv, float* __restrict__ O)
{
    int bh = blockIdx.x;
    int b = bh / NHEAD, h = bh - b*NHEAD;
    extern __shared__ float sm[];
    float* vs = sm;             // [198][64]
    float* ps = sm + NSEQ*64;   // [32][198]
    int tid = threadIdx.x;
    const float* vbase = qkv + (size_t)b*NSEQ*(3*CDIM) + 2*CDIM + h*HD;
    for (int i = tid; i < NSEQ*64; i += 256) {
        int t = i >> 6, d = i & 63;
        vs[i] = vbase[(size_t)t*(3*CDIM) + d];
    }
    const float* Sb = S + (size_t)bh*(NSEQ*NSEQ);
    float* Ob = O + (size_t)b*NSEQ*CDIM + h*HD;
    int d = tid & 63, qg = tid >> 6;
    for (int q0 = 0; q0 < NSEQ; q0 += 32) {
        int rows = NSEQ - q0; if (rows > 32) rows = 32;
        __syncthreads();
        for (int i = tid; i < rows*NSEQ; i += 256) ps[i] = Sb[(size_t)q0*NSEQ + i];
        __syncthreads();
        for (int ql = qg; ql < rows; ql += 8) {
            int q2l = ql + 4;
            if (q2l < rows) {
                float a1=0.f, a2=0.f;
                const float* p1 = ps + ql*NSEQ;
                const float* p2 = ps + q2l*NSEQ;
                for (int kk=0; kk<NSEQ; kk++) {
                    float vv = vs[kk*64+d];
                    a1 = fmaf(p1[kk], vv, a1);
                    a2 = fmaf(p2[kk], vv, a2);
                }
                Ob[(size_t)(q0+ql)*CDIM + d]  = a1;
                Ob[(size_t)(q0+q2l)*CDIM + d] = a2;
            } else {
                float a1=0.f;
                const float* p1 = ps + ql*NSEQ;
                for (int kk=0; kk<NSEQ; kk++) a1 = fmaf(p1[kk], vs[kk*64+d], a1);
                Ob[(size_t)(q0+ql)*CDIM + d] = a1;
            }
        }
    }
}

// ---------------- head features: 9 rectangle sums per (b,c) ----------------
__launch_bounds__(256)
__global__ void sfeat_kernel(const float* __restrict__ T, float* __restrict__ SF)
{
    int i = blockIdx.x*256 + threadIdx.x;
    if (i >= NB*CDIM) return;
    int b = i / CDIM, c = i - b*CDIM;
    const float* base = T + ((size_t)b*NSEQ + 1)*CDIM + c;
    float tot=0.f, r0=0.f, r13=0.f, c0s=0.f, c13s=0.f;
    for (int u=0; u<14; u++) {
        for (int v=0; v<14; v++) {
            float val = base[(size_t)(u*14+v)*CDIM];
            tot += val;
            if (u==0)  r0  += val;
            if (u==13) r13 += val;
            if (v==0)  c0s += val;
            if (v==13) c13s += val;
        }
    }
    float x00 = base[0];
    float x0e = base[(size_t)13*CDIM];
    float xe0 = base[(size_t)(13*14)*CDIM];
    float xee = base[(size_t)(13*14+13)*CDIM];
    float* o = SF + (size_t)b*6912 + c*9;
    for (int dy=0; dy<3; dy++)
        for (int dx=0; dx<3; dx++) {
            float s = tot;
            if (dy==0) s -= r13;
            if (dy==2) s -= r0;
            if (dx==0) s -= c13s;
            if (dx==2) s -= c0s;
            if (dy==0 && dx==0) s += xee;
            if (dy==0 && dx==2) s += xe0;
            if (dy==2 && dx==0) s += x0e;
            if (dy==2 && dx==2) s += x00;
            o[dy*3+dx] = s;
        }
}

// ---------------- logits ----------------
__launch_bounds__(256)
__global__ void head_kernel(const float* __restrict__ SF, const float* __restrict__ W,
                            const float* __restrict__ bias, float* __restrict__ out)
{
    int gw = (blockIdx.x*256 + threadIdx.x) >> 5;
    int lane = threadIdx.x & 31;
    if (gw >= NB*200) return;
    int b = gw / 200, cls = gw - b*200;
    const float* a = SF + (size_t)b*6912;
    const float* w = W + (size_t)cls*6912;
    float s = 0.f;
    for (int k = lane; k < 6912; k += 32) s = fmaf(a[k], w[k], s);
#pragma unroll
    for (int o=16;o;o>>=1) s += __shfl_xor_sync(0xffffffffu, s, o);
    if (lane==0) out[gw] = s*(1.f/196.f) + bias[cls];
}

// ---------------- final mask outputs ----------------
__launch_bounds__(256)
__global__ void final_mask(const float* __restrict__ Mlayers, const float* __restrict__ gk,
                           float* __restrict__ out)
{
    int b = blockIdx.x;
    __shared__ float ma[196];
    __shared__ float red[8];
    int tid = threadIdx.x;
    if (tid < 196) {
        float s = 0.f;
        for (int l=9; l<12; l++) s += Mlayers[((size_t)l*NB + b)*NSEQ + 1 + tid];
        ma[tid] = s * (1.f/3.f);
    }
    __syncthreads();
    float part = (tid < 196) ? ma[tid] : 0.f;
#pragma unroll
    for (int o=16;o;o>>=1) part += __shfl_xor_sync(0xffffffffu, part, o);
    if ((tid&31)==0) red[tid>>5] = part;
    __syncthreads();
    if (tid==0){ float t=0.f; for(int i=0;i<8;i++) t+=red[i]; out[12800 + b] = t*(1.f/196.f); }
    float t3 = 0.f;
    if (tid < 196) {
        int y = tid/14, x = tid - y*14;
        float m = 0.f;
        for (int dy=0; dy<3; dy++)
            for (int dx=0; dx<3; dx++) {
                int yy = y+dy-1, xx = x+dx-1;
                if (yy>=0 && yy<14 && xx>=0 && xx<14)
                    m += gk[dy*3+dx]*ma[yy*14+xx];
            }
        t3 = (1.f - m)*m;
    }
    __syncthreads();
#pragma unroll
    for (int o=16;o;o>>=1) t3 += __shfl_xor_sync(0xffffffffu, t3, o);
    if ((tid&31)==0) red[tid>>5] = t3;
    __syncthreads();
    if (tid==0){ float t=0.f; for(int i=0;i<8;i++) t+=red[i]; out[12864 + b] = t*(1.f/196.f); }
}

// ---------------- launch ----------------
extern "C" void kernel_launch(void* const* d_in, const int* in_sizes, int n_in,
                              void* d_out, int out_size)
{
    const float* x       = (const float*)d_in[0];
    const float* patch_w = (const float*)d_in[1];
    const float* patch_b = (const float*)d_in[2];
    const float* cls_tok = (const float*)d_in[3];
    const float* loc_tok = (const float*)d_in[4];
    const float* pos_emb = (const float*)d_in[5];
    const float* loc_emb = (const float*)d_in[6];
    const float* ln1_w   = (const float*)d_in[7];
    const float* ln1_b   = (const float*)d_in[8];
    const float* qkv_w   = (const float*)d_in[9];
    const float* proj_w  = (const float*)d_in[10];
    const float* proj_b  = (const float*)d_in[11];
    const float* ln2_w   = (const float*)d_in[12];
    const float* ln2_b   = (const float*)d_in[13];
    const float* fc1_w   = (const float*)d_in[14];
    const float* fc1_b   = (const float*)d_in[15];
    const float* fc2_w   = (const float*)d_in[16];
    const float* fc2_b   = (const float*)d_in[17];
    const float* norm_w  = (const float*)d_in[18];
    const float* norm_b  = (const float*)d_in[19];
    const float* head_w  = (const float*)d_in[20];
    const float* head_b  = (const float*)d_in[21];
    const float* gk      = (const float*)d_in[22];
    float* out = (float*)d_out;

    float *t, *a, *qkvb, *attn, *o, *hbuf, *maskb, *sfeat;
    cudaGetSymbolAddress((void**)&t,     g_t);
    cudaGetSymbolAddress((void**)&a,     g_a);
    cudaGetSymbolAddress((void**)&qkvb,  g_qkv);
    cudaGetSymbolAddress((void**)&attn,  g_attn);
    cudaGetSymbolAddress((void**)&o,     g_o);
    cudaGetSymbolAddress((void**)&hbuf,  g_h);
    cudaGetSymbolAddress((void**)&maskb, g_mask);
    cudaGetSymbolAddress((void**)&sfeat, g_sfeat);

    cudaFuncSetAttribute(attn_fused, cudaFuncAttributeMaxDynamicSharedMemorySize, SMEM_SCORES);
    cudaFuncSetAttribute(attn_v,     cudaFuncAttributeMaxDynamicSharedMemorySize, SMEM_AV);

    // patch embed
    im2col_patch<<<(NPAT*CDIM+255)/256, 256>>>(x, a);
    gemm_fp16<EP_BIAS><<<dim3(6,98), 256>>>(a, patch_w, patch_b, nullptr, o, NPAT, CDIM, CDIM);
    assemble_t<<<(NTOK*CDIM+255)/256, 256>>>(o, cls_tok, loc_tok, pos_emb, loc_emb, t);

    for (int d=0; d<12; d++) {
        ln_kernel<<<NTOK, 256>>>(t, ln1_w + d*CDIM, ln1_b + d*CDIM, a);
        gemm_fp16<EP_NONE><<<dim3(18,99), 256>>>(a, qkv_w + (size_t)d*3*CDIM*CDIM, nullptr, nullptr,
                                                 qkvb, NTOK, 3*CDIM, CDIM);
        if (d >= 9)
            mask_pre<<<NB, 256>>>(qkvb, maskb + (size_t)d*NB*NSEQ);
        attn_fused<<<NB*NHEAD, 256, SMEM_SCORES>>>(qkvb, attn, maskb + (size_t)d*NB*NSEQ, (d>=9)?1:0);
        attn_v<<<NB*NHEAD, 256, SMEM_AV>>>(attn, qkvb, o);
        gemm_fp16<EP_BIAS_RES><<<dim3(6,99), 256>>>(o, proj_w + (size_t)d*CDIM*CDIM, proj_b + d*CDIM,
                                                    t, t, NTOK, CDIM, CDIM);
        ln_kernel<<<NTOK, 256>>>(t, ln2_w + d*CDIM, ln2_b + d*CDIM, a);
        gemm_fp16<EP_BIAS_GELU><<<dim3(24,99), 256>>>(a, fc1_w + (size_t)d*4*CDIM*CDIM, fc1_b + d*4*CDIM,
                                                      nullptr, hbuf, NTOK, 4*CDIM, CDIM);
        gemm_fp16<EP_BIAS_RES><<<dim3(6,99), 256>>>(hbuf, fc2_w + (size_t)d*CDIM*4*CDIM, fc2_b + d*CDIM,
                                                    t, t, NTOK, CDIM, 4*CDIM);
    }

    ln_kernel<<<NTOK, 256>>>(t, norm_w, norm_b, a);
    sfeat_kernel<<<(NB*CDIM+255)/256, 256>>>(a, sfeat);
    head_kernel<<<(NB*200*32+255)/256, 256>>>(sfeat, head_w, head_b, out);
    final_mask<<<NB, 256>>>(maskb, gk, out);
}

// round 4
// speedup vs baseline: 5.4384x; 1.4464x over previous
#include <cuda_runtime.h>
#include <cuda_fp16.h>
#include <math.h>

// ---------------- problem constants ----------------
#define NB    64
#define NSEQ  198
#define NTOK  (NB*NSEQ)      // 12672 = 99*128
#define NPAT  (NB*196)       // 12544 = 98*128
#define CDIM  768
#define NHEAD 12
#define HD    64

// weight fp16 pool offsets
#define W_PATCH 0
#define W_QKV   589824
#define W_PROJ  21823488
#define W_FC1   28901376
#define W_FC2   57212928
#define W_TOTAL 85524480

// ---------------- scratch (device globals; no allocs allowed) ----------------
__device__ float  g_t   [(size_t)NTOK*CDIM];    // token stream (fp32 residual)
__device__ float  g_o   [(size_t)NTOK*CDIM];    // patch gemm out (fp32)
__device__ float  g_mask[(size_t)12*NB*NSEQ];
__device__ float  g_sfeat[(size_t)NB*6912];
__device__ __half g_ah  [(size_t)NTOK*CDIM];    // ln out / im2col (fp16)
__device__ __half g_qkvh[(size_t)NTOK*3*CDIM];
__device__ __half g_oh  [(size_t)NTOK*CDIM];    // attn out (fp16)
__device__ __half g_hh  [(size_t)NTOK*4*CDIM];  // mlp hidden (fp16)
__device__ __half g_wh  [(size_t)W_TOTAL];      // fp16 weights

enum { EP_NONE=0, EP_BIAS=1, EP_BIAS_RES=2, EP_BIAS_GELU=3 };

// ---------------- mma helpers ----------------
__device__ __forceinline__ void mma_fp16(float c[4], const unsigned a[4], const unsigned b[2]){
    asm volatile("mma.sync.aligned.m16n8k16.row.col.f32.f16.f16.f32 "
        "{%0,%1,%2,%3}, {%4,%5,%6,%7}, {%8,%9}, {%0,%1,%2,%3};\n"
        : "+f"(c[0]),"+f"(c[1]),"+f"(c[2]),"+f"(c[3])
        : "r"(a[0]),"r"(a[1]),"r"(a[2]),"r"(a[3]), "r"(b[0]),"r"(b[1]));
}
__device__ __forceinline__ void mma_fp16_k8(float c[4], const unsigned a[2], unsigned b0){
    asm volatile("mma.sync.aligned.m16n8k8.row.col.f32.f16.f16.f32 "
        "{%0,%1,%2,%3}, {%4,%5}, {%6}, {%0,%1,%2,%3};\n"
        : "+f"(c[0]),"+f"(c[1]),"+f"(c[2]),"+f"(c[3])
        : "r"(a[0]),"r"(a[1]), "r"(b0));
}

// ---------------- f32 -> f16 convert ----------------
__global__ void f2h_kernel(const float* __restrict__ src, __half* __restrict__ dst, int n4){
    int i = blockIdx.x*256 + threadIdx.x;
    if (i < n4){
        float4 v = ((const float4*)src)[i];
        __half2 a = __floats2half2_rn(v.x, v.y);
        __half2 b = __floats2half2_rn(v.z, v.w);
        ((__half2*)dst)[i*2  ] = a;
        ((__half2*)dst)[i*2+1] = b;
    }
}

// ---------------- fp16-input GEMM-NT: C[M,N] = A[M,K]*B[N,K]^T ----------------
// 128x128x32 tile, 8 warps (warp tile 32x64), double-buffered, no bounds checks.
template<int EPI, typename OT>
__global__ void __launch_bounds__(256) gemm_h(
    const __half* __restrict__ A, const __half* __restrict__ B,
    const float* __restrict__ bias, const float* __restrict__ res,
    OT* __restrict__ C, int M, int N, int K)
{
    __shared__ __half As[2][128][40];
    __shared__ __half Bs[2][128][40];
    const int tid=threadIdx.x, warp=tid>>5, lane=tid&31;
    const int wm=warp>>1, wn=warp&1;
    const int gid=lane>>2, tg=lane&3;
    const int bm=blockIdx.y*128, bn=blockIdx.x*128;
    const int r0 = tid>>2, c8 = (tid&3)*8;

    const __half* Agp = A + (size_t)(bm + r0)*K + c8;
    const __half* Bgp = B + (size_t)(bn + r0)*K + c8;

    float acc[2][8][4];
#pragma unroll
    for(int i=0;i<2;i++)
#pragma unroll
        for(int j=0;j<8;j++)
#pragma unroll
            for(int q=0;q<4;q++) acc[i][j][q]=0.f;

    uint4 ra[2], rb[2];
#pragma unroll
    for(int i=0;i<2;i++){
        ra[i]=*(const uint4*)(Agp + (size_t)(64*i)*K);
        rb[i]=*(const uint4*)(Bgp + (size_t)(64*i)*K);
    }
    const int nit = K >> 5;
#pragma unroll
    for(int i=0;i<2;i++){
        *(uint4*)&As[0][r0+64*i][c8] = ra[i];
        *(uint4*)&Bs[0][r0+64*i][c8] = rb[i];
    }
    __syncthreads();

    for(int it=0; it<nit; it++){
        const int cur = it&1;
        if (it+1 < nit){
            const size_t off = (size_t)(it+1)*32;
#pragma unroll
            for(int i=0;i<2;i++){
                ra[i]=*(const uint4*)(Agp + (size_t)(64*i)*K + off);
                rb[i]=*(const uint4*)(Bgp + (size_t)(64*i)*K + off);
            }
        }
#pragma unroll
        for(int ks=0; ks<2; ks++){
            const int kb = ks*16 + 2*tg;
            unsigned af[2][4], bf[8][2];
#pragma unroll
            for(int i=0;i<2;i++){
                int r = wm*32 + i*16 + gid;
                af[i][0]=*(const unsigned*)&As[cur][r  ][kb];
                af[i][1]=*(const unsigned*)&As[cur][r+8][kb];
                af[i][2]=*(const unsigned*)&As[cur][r  ][kb+8];
                af[i][3]=*(const unsigned*)&As[cur][r+8][kb+8];
            }
#pragma unroll
            for(int j=0;j<8;j++){
                int c = wn*64 + j*8 + gid;
                bf[j][0]=*(const unsigned*)&Bs[cur][c][kb];
                bf[j][1]=*(const unsigned*)&Bs[cur][c][kb+8];
            }
#pragma unroll
            for(int i=0;i<2;i++)
#pragma unroll
                for(int j=0;j<8;j++)
                    mma_fp16(acc[i][j], af[i], bf[j]);
        }
        if (it+1 < nit){
            const int nxt = cur^1;
#pragma unroll
            for(int i=0;i<2;i++){
                *(uint4*)&As[nxt][r0+64*i][c8] = ra[i];
                *(uint4*)&Bs[nxt][r0+64*i][c8] = rb[i];
            }
        }
        __syncthreads();
    }

#pragma unroll
    for(int i=0;i<2;i++){
#pragma unroll
        for(int rr=0;rr<2;rr++){
            int row = bm + wm*32 + i*16 + gid + rr*8;
#pragma unroll
            for(int j=0;j<8;j++){
                int col = bn + wn*64 + j*8 + tg*2;
                float v0 = acc[i][j][rr*2+0];
                float v1 = acc[i][j][rr*2+1];
                if (EPI == EP_BIAS) { v0 += bias[col]; v1 += bias[col+1]; }
                else if (EPI == EP_BIAS_RES) {
                    v0 += bias[col]   + res[(size_t)row*N+col];
                    v1 += bias[col+1] + res[(size_t)row*N+col+1];
                }
                else if (EPI == EP_BIAS_GELU) {
                    v0 += bias[col];   v1 += bias[col+1];
                    v0 = 0.5f*v0*(1.f + erff(v0*0.70710678118654752f));
                    v1 = 0.5f*v1*(1.f + erff(v1*0.70710678118654752f));
                }
                if (sizeof(OT)==2) {
                    __half2 hv = __floats2half2_rn(v0, v1);
                    *(__half2*)((__half*)C + (size_t)row*N + col) = hv;
                } else {
                    *(float2*)((float*)C + (size_t)row*N + col) = make_float2(v0,v1);
                }
            }
        }
    }
}

// ---------------- patch im2col -> fp16 ----------------
__global__ void im2col_patch(const float* __restrict__ x, __half* __restrict__ A)
{
    int i = blockIdx.x*256 + threadIdx.x;
    if (i >= NPAT*CDIM) return;
    int p = i / CDIM, kidx = i - p*CDIM;
    int b = p / 196, pp = p - b*196;
    int py = pp / 14, px = pp - py*14;
    int c = kidx >> 8;
    int rem = kidx & 255;
    int iy = rem >> 4, ix = rem & 15;
    A[i] = __float2half(x[(((size_t)b*3 + c)*224 + (py*16+iy))*224 + (px*16+ix)]);
}

// ---------------- assemble token stream ----------------
__global__ void assemble_t(const float* __restrict__ P, const float* __restrict__ cls,
                           const float* __restrict__ loc, const float* __restrict__ pos,
                           const float* __restrict__ loce, float* __restrict__ T)
{
    int i = blockIdx.x*256 + threadIdx.x;
    if (i >= NTOK*CDIM) return;
    int tok = i / CDIM, c = i - tok*CDIM;
    int b = tok / NSEQ, tt = tok - b*NSEQ;
    float v;
    if (tt == 0)          v = cls[c] + pos[c];
    else if (tt == 197)   v = loc[c] + loce[c];
    else                  v = P[((size_t)b*196 + tt-1)*CDIM + c] + pos[(size_t)tt*CDIM + c];
    T[i] = v;
}

// ---------------- layernorm: fp32 in, fp16 out ----------------
__launch_bounds__(256)
__global__ void ln_kernel(const float* __restrict__ X, const float* __restrict__ w,
                          const float* __restrict__ bb, __half* __restrict__ Y)
{
    int row = blockIdx.x;
    const float* x = X + (size_t)row * CDIM;
    __half* y = Y + (size_t)row * CDIM;
    int tid = threadIdx.x;
    float v0 = x[tid], v1 = x[tid+256], v2 = x[tid+512];
    __shared__ float red[8];
    __shared__ float mrs[2];
    float s = v0+v1+v2;
#pragma unroll
    for (int o=16;o;o>>=1) s += __shfl_xor_sync(0xffffffffu, s, o);
    if ((tid&31)==0) red[tid>>5] = s;
    __syncthreads();
    if (tid==0){ float t=0.f; for(int i=0;i<8;i++) t+=red[i]; mrs[0]=t*(1.f/768.f); }
    __syncthreads();
    float m = mrs[0];
    float d0=v0-m, d1=v1-m, d2=v2-m;
    float q = d0*d0+d1*d1+d2*d2;
#pragma unroll
    for (int o=16;o;o>>=1) q += __shfl_xor_sync(0xffffffffu, q, o);
    __syncthreads();
    if ((tid&31)==0) red[tid>>5] = q;
    __syncthreads();
    if (tid==0){ float t=0.f; for(int i=0;i<8;i++) t+=red[i]; mrs[1]=rsqrtf(t*(1.f/768.f)+1e-5f); }
    __syncthreads();
    float rs = mrs[1];
    y[tid]     = __float2half(d0*rs*w[tid]     + bb[tid]);
    y[tid+256] = __float2half(d1*rs*w[tid+256] + bb[tid+256]);
    y[tid+512] = __float2half(d2*rs*w[tid+512] + bb[tid+512]);
}

// ---------------- mask precompute (fp16 qkv) ----------------
__launch_bounds__(256)
__global__ void mask_pre(const __half* __restrict__ qkv, float* __restrict__ mask)
{
    int b = blockIdx.x;
    __shared__ float q197[CDIM];
    int tid = threadIdx.x;
    const __half* qrow = qkv + ((size_t)b*NSEQ + 197)*(3*CDIM);
    for (int i=tid;i<CDIM;i+=256) q197[i]=__half2float(qrow[i]);
    __syncthreads();
    int warp=tid>>5, lane=tid&31;
    for (int k=warp; k<NSEQ; k+=8){
        const __half* krow = qkv + ((size_t)b*NSEQ + k)*(3*CDIM) + CDIM;
        float s=0.f;
        for (int d=lane; d<CDIM; d+=32) s = fmaf(q197[d], __half2float(krow[d]), s);
#pragma unroll
        for (int o=16;o;o>>=1) s += __shfl_xor_sync(0xffffffffu, s, o);
        if (lane==0) mask[(size_t)b*NSEQ + k] = 1.f/(1.f + __expf(-s*(0.125f/12.f)));
    }
}

// ---------------- fused tensor-core attention per (b,h) ----------------
// smem: Ss fp32[208][200] | Qs fp16[208][72] (reused as Vs fp16[64][216]) | Ks fp16[208][72]
#define ATT_SMEM (166400 + 29952 + 29952)
__global__ void __launch_bounds__(256) attn_mma(
    const __half* __restrict__ qkv, const float* __restrict__ mask,
    int use_mask, __half* __restrict__ O)
{
    int bh = blockIdx.x;
    int b = bh / NHEAD, h = bh - b*NHEAD;
    extern __shared__ char smem[];
    float*  Ss = (float*)smem;                    // [208][200]
    __half* Qs = (__half*)(smem + 166400);        // [208][72]
    __half* Ks = (__half*)(smem + 166400+29952);  // [208][72]
    const int tid=threadIdx.x, warp=tid>>5, lane=tid&31;
    const int gid=lane>>2, tg=lane&3;
    const __half* base = qkv + (size_t)b*NSEQ*(3*CDIM) + h*HD;
    const __half hz = __float2half(0.f);

    // phase 1: load Q, K (zero-pad rows 198..207)
    for (int i = tid; i < 208*64; i += 256){
        int t = i>>6, d = i&63;
        __half q = hz, k = hz;
        if (t < NSEQ){
            q = base[(size_t)t*(3*CDIM) + d];
            k = base[(size_t)t*(3*CDIM) + CDIM + d];
        }
        Qs[t*72+d] = q; Ks[t*72+d] = k;
    }
    __syncthreads();

    // phase 2: S = Q K^T * scale  (13 m-tiles x 25 n-tiles x 4 k16)
    for (int mt = warp; mt < 13; mt += 8){
        int m0 = mt*16;
        unsigned af[4][4];
#pragma unroll
        for (int ks=0; ks<4; ks++){
            int kb = ks*16 + 2*tg;
            af[ks][0] = *(const unsigned*)&Qs[(m0+gid  )*72 + kb  ];
            af[ks][1] = *(const unsigned*)&Qs[(m0+gid+8)*72 + kb  ];
            af[ks][2] = *(const unsigned*)&Qs[(m0+gid  )*72 + kb+8];
            af[ks][3] = *(const unsigned*)&Qs[(m0+gid+8)*72 + kb+8];
        }
        for (int nt = 0; nt < 25; nt++){
            int n0 = nt*8;
            float acc[4] = {0.f,0.f,0.f,0.f};
#pragma unroll
            for (int ks=0; ks<4; ks++){
                int kb = ks*16 + 2*tg;
                unsigned bb[2];
                bb[0] = *(const unsigned*)&Ks[(n0+gid)*72 + kb  ];
                bb[1] = *(const unsigned*)&Ks[(n0+gid)*72 + kb+8];
                mma_fp16(acc, af[ks], bb);
            }
            int r = m0 + gid, c = n0 + tg*2;
            Ss[(size_t)r*200 + c  ] = acc[0]*0.125f;
            Ss[(size_t)r*200 + c+1] = acc[1]*0.125f;
            Ss[(size_t)(r+8)*200 + c  ] = acc[2]*0.125f;
            Ss[(size_t)(r+8)*200 + c+1] = acc[3]*0.125f;
        }
    }
    __syncthreads();

    // phase 3a: load V transposed into Qs region: Vs[d][k], zero-pad k>=198
    __half* Vs = Qs;
    for (int i = tid; i < 64*216; i += 256){
        int d = i/216, k = i - d*216;
        __half v = hz;
        if (k < NSEQ) v = base[(size_t)k*(3*CDIM) + 2*CDIM + d];
        Vs[d*216 + k] = v;
    }
    // phase 3b: softmax rows (+mask), zero pad cols 198,199
    const float* mrow = mask + (size_t)b*NSEQ;
    for (int row = warp; row < NSEQ; row += 8){
        float* Sr = Ss + (size_t)row*200;
        float v[7]; float mx = -1e30f;
#pragma unroll
        for (int j=0;j<7;j++){
            int col = lane + 32*j;
            v[j] = (col < NSEQ) ? Sr[col] : -1e30f;
            mx = fmaxf(mx, v[j]);
        }
#pragma unroll
        for (int o=16;o;o>>=1) mx = fmaxf(mx, __shfl_xor_sync(0xffffffffu, mx, o));
        float sum = 0.f;
#pragma unroll
        for (int j=0;j<7;j++){
            int col = lane + 32*j;
            v[j] = (col < NSEQ) ? __expf(v[j]-mx) : 0.f;
            sum += v[j];
        }
#pragma unroll
        for (int o=16;o;o>>=1) sum += __shfl_xor_sync(0xffffffffu, sum, o);
        float inv = 1.f/sum;
#pragma unroll
        for (int j=0;j<7;j++){
            int col = lane + 32*j;
            if (col < NSEQ){
                float p = v[j]*inv;
                if (use_mask) p *= mrow[col];
                Sr[col] = p;
            }
        }
        if (lane < 2) Sr[NSEQ + lane] = 0.f;
    }
    __syncthreads();

    // phase 4: O = P V   (13 m-tiles x 8 n-tiles, 12 k16 + 1 k8)
    __half* Oh = O + (size_t)b*NSEQ*CDIM + h*HD;
    for (int mt = warp; mt < 13; mt += 8){
        int m0 = mt*16;
        float acc[8][4];
#pragma unroll
        for (int j=0;j<8;j++)
#pragma unroll
            for (int q=0;q<4;q++) acc[j][q]=0.f;
        for (int ks = 0; ks < 12; ks++){
            int k0 = ks*16 + 2*tg;
            unsigned af[4];
            {
                float2 p0 = *(const float2*)&Ss[(size_t)(m0+gid  )*200 + k0  ];
                float2 p1 = *(const float2*)&Ss[(size_t)(m0+gid+8)*200 + k0  ];
                float2 p2 = *(const float2*)&Ss[(size_t)(m0+gid  )*200 + k0+8];
                float2 p3 = *(const float2*)&Ss[(size_t)(m0+gid+8)*200 + k0+8];
                __half2 h0=__floats2half2_rn(p0.x,p0.y), h1=__floats2half2_rn(p1.x,p1.y);
                __half2 h2=__floats2half2_rn(p2.x,p2.y), h3=__floats2half2_rn(p3.x,p3.y);
                af[0]=*(unsigned*)&h0; af[1]=*(unsigned*)&h1;
                af[2]=*(unsigned*)&h2; af[3]=*(unsigned*)&h3;
            }
            int kv = ks*16 + 2*tg;
#pragma unroll
            for (int nt = 0; nt < 8; nt++){
                unsigned bb[2];
                bb[0] = *(const unsigned*)&Vs[(nt*8+gid)*216 + kv  ];
                bb[1] = *(const unsigned*)&Vs[(nt*8+gid)*216 + kv+8];
                mma_fp16(acc[nt], af, bb);
            }
        }
        {   // k8 tail: k 192..199
            int k0 = 192 + 2*tg;
            float2 p0 = *(const float2*)&Ss[(size_t)(m0+gid  )*200 + k0];
            float2 p1 = *(const float2*)&Ss[(size_t)(m0+gid+8)*200 + k0];
            __half2 h0=__floats2half2_rn(p0.x,p0.y), h1=__floats2half2_rn(p1.x,p1.y);
            unsigned af2[2]; af2[0]=*(unsigned*)&h0; af2[1]=*(unsigned*)&h1;
#pragma unroll
            for (int nt = 0; nt < 8; nt++){
                unsigned b0 = *(const unsigned*)&Vs[(nt*8+gid)*216 + k0];
                mma_fp16_k8(acc[nt], af2, b0);
            }
        }
#pragma unroll
        for (int rr = 0; rr < 2; rr++){
            int q = m0 + gid + rr*8;
            if (q < NSEQ){
#pragma unroll
                for (int nt = 0; nt < 8; nt++){
                    __half2 hv = __floats2half2_rn(acc[nt][rr*2], acc[nt][rr*2+1]);
                    *(__half2*)&Oh[(size_t)q*CDIM + nt*8 + tg*2] = hv;
                }
            }
        }
    }
}

// ---------------- head features: 9 rectangle sums per (b,c) ----------------
__launch_bounds__(256)
__global__ void sfeat_kernel(const __half* __restrict__ T, float* __restrict__ SF)
{
    int i = blockIdx.x*256 + threadIdx.x;
    if (i >= NB*CDIM) return;
    int b = i / CDIM, c = i - b*CDIM;
    const __half* base = T + ((size_t)b*NSEQ + 1)*CDIM + c;
    float tot=0.f, r0=0.f, r13=0.f, c0s=0.f, c13s=0.f;
    for (int u=0; u<14; u++) {
        for (int v=0; v<14; v++) {
            float val = __half2float(base[(size_t)(u*14+v)*CDIM]);
            tot += val;
            if (u==0)  r0  += val;
            if (u==13) r13 += val;
            if (v==0)  c0s += val;
            if (v==13) c13s += val;
        }
    }
    float x00 = __half2float(base[0]);
    float x0e = __half2float(base[(size_t)13*CDIM]);
    float xe0 = __half2float(base[(size_t)(13*14)*CDIM]);
    float xee = __half2float(base[(size_t)(13*14+13)*CDIM]);
    float* o = SF + (size_t)b*6912 + c*9;
    for (int dy=0; dy<3; dy++)
        for (int dx=0; dx<3; dx++) {
            float s = tot;
            if (dy==0) s -= r13;
            if (dy==2) s -= r0;
            if (dx==0) s -= c13s;
            if (dx==2) s -= c0s;
            if (dy==0 && dx==0) s += xee;
            if (dy==0 && dx==2) s += xe0;
            if (dy==2 && dx==0) s += x0e;
            if (dy==2 && dx==2) s += x00;
            o[dy*3+dx] = s;
        }
}

// ---------------- logits ----------------
__launch_bounds__(256)
__global__ void head_kernel(const float* __restrict__ SF, const float* __restrict__ W,
                            const float* __restrict__ bias, float* __restrict__ out)
{
    int gw = (blockIdx.x*256 + threadIdx.x) >> 5;
    int lane = threadIdx.x & 31;
    if (gw >= NB*200) return;
    int b = gw / 200, cls = gw - b*200;
    const float* a = SF + (size_t)b*6912;
    const float* w = W + (size_t)cls*6912;
    float s = 0.f;
    for (int k = lane; k < 6912; k += 32) s = fmaf(a[k], w[k], s);
#pragma unroll
    for (int o=16;o;o>>=1) s += __shfl_xor_sync(0xffffffffu, s, o);
    if (lane==0) out[gw] = s*(1.f/196.f) + bias[cls];
}

// ---------------- final mask outputs ----------------
__launch_bounds__(256)
__global__ void final_mask(const float* __restrict__ Mlayers, const float* __restrict__ gk,
                           float* __restrict__ out)
{
    int b = blockIdx.x;
    __shared__ float ma[196];
    __shared__ float red[8];
    int tid = threadIdx.x;
    if (tid < 196) {
        float s = 0.f;
        for (int l=9; l<12; l++) s += Mlayers[((size_t)l*NB + b)*NSEQ + 1 + tid];
        ma[tid] = s * (1.f/3.f);
    }
    __syncthreads();
    float part = (tid < 196) ? ma[tid] : 0.f;
#pragma unroll
    for (int o=16;o;o>>=1) part += __shfl_xor_sync(0xffffffffu, part, o);
    if ((tid&31)==0) red[tid>>5] = part;
    __syncthreads();
    if (tid==0){ float t=0.f; for(int i=0;i<8;i++) t+=red[i]; out[12800 + b] = t*(1.f/196.f); }
    float t3 = 0.f;
    if (tid < 196) {
        int y = tid/14, x = tid - y*14;
        float m = 0.f;
        for (int dy=0; dy<3; dy++)
            for (int dx=0; dx<3; dx++) {
                int yy = y+dy-1, xx = x+dx-1;
                if (yy>=0 && yy<14 && xx>=0 && xx<14)
                    m += gk[dy*3+dx]*ma[yy*14+xx];
            }
        t3 = (1.f - m)*m;
    }
    __syncthreads();
#pragma unroll
    for (int o=16;o;o>>=1) t3 += __shfl_xor_sync(0xffffffffu, t3, o);
    if ((tid&31)==0) red[tid>>5] = t3;
    __syncthreads();
    if (tid==0){ float t=0.f; for(int i=0;i<8;i++) t+=red[i]; out[12864 + b] = t*(1.f/196.f); }
}

// ---------------- launch ----------------
extern "C" void kernel_launch(void* const* d_in, const int* in_sizes, int n_in,
                              void* d_out, int out_size)
{
    const float* x       = (const float*)d_in[0];
    const float* patch_w = (const float*)d_in[1];
    const float* patch_b = (const float*)d_in[2];
    const float* cls_tok = (const float*)d_in[3];
    const float* loc_tok = (const float*)d_in[4];
    const float* pos_emb = (const float*)d_in[5];
    const float* loc_emb = (const float*)d_in[6];
    const float* ln1_w   = (const float*)d_in[7];
    const float* ln1_b   = (const float*)d_in[8];
    const float* qkv_w   = (const float*)d_in[9];
    const float* proj_w  = (const float*)d_in[10];
    const float* proj_b  = (const float*)d_in[11];
    const float* ln2_w   = (const float*)d_in[12];
    const float* ln2_b   = (const float*)d_in[13];
    const float* fc1_w   = (const float*)d_in[14];
    const float* fc1_b   = (const float*)d_in[15];
    const float* fc2_w   = (const float*)d_in[16];
    const float* fc2_b   = (const float*)d_in[17];
    const float* norm_w  = (const float*)d_in[18];
    const float* norm_b  = (const float*)d_in[19];
    const float* head_w  = (const float*)d_in[20];
    const float* head_b  = (const float*)d_in[21];
    const float* gk      = (const float*)d_in[22];
    float* out = (float*)d_out;

    float *t, *o, *maskb, *sfeat;
    __half *ah, *qkvh, *oh, *hh, *wh;
    cudaGetSymbolAddress((void**)&t,     g_t);
    cudaGetSymbolAddress((void**)&o,     g_o);
    cudaGetSymbolAddress((void**)&maskb, g_mask);
    cudaGetSymbolAddress((void**)&sfeat, g_sfeat);
    cudaGetSymbolAddress((void**)&ah,    g_ah);
    cudaGetSymbolAddress((void**)&qkvh,  g_qkvh);
    cudaGetSymbolAddress((void**)&oh,    g_oh);
    cudaGetSymbolAddress((void**)&hh,    g_hh);
    cudaGetSymbolAddress((void**)&wh,    g_wh);

    cudaFuncSetAttribute(attn_mma, cudaFuncAttributeMaxDynamicSharedMemorySize, ATT_SMEM);

    // convert weights to fp16 pool
    f2h_kernel<<<(589824/4+255)/256,   256>>>(patch_w, wh + W_PATCH, 589824/4);
    f2h_kernel<<<(21233664/4+255)/256, 256>>>(qkv_w,   wh + W_QKV,   21233664/4);
    f2h_kernel<<<(7077888/4+255)/256,  256>>>(proj_w,  wh + W_PROJ,  7077888/4);
    f2h_kernel<<<(28311552/4+255)/256, 256>>>(fc1_w,   wh + W_FC1,   28311552/4);
    f2h_kernel<<<(28311552/4+255)/256, 256>>>(fc2_w,   wh + W_FC2,   28311552/4);

    // patch embed
    im2col_patch<<<(NPAT*CDIM+255)/256, 256>>>(x, ah);
    gemm_h<EP_BIAS,float><<<dim3(6,98), 256>>>(ah, wh + W_PATCH, patch_b, nullptr, o, NPAT, CDIM, CDIM);
    assemble_t<<<(NTOK*CDIM+255)/256, 256>>>(o, cls_tok, loc_tok, pos_emb, loc_emb, t);

    for (int d=0; d<12; d++) {
        ln_kernel<<<NTOK, 256>>>(t, ln1_w + d*CDIM, ln1_b + d*CDIM, ah);
        gemm_h<EP_NONE,__half><<<dim3(18,99), 256>>>(ah, wh + W_QKV + (size_t)d*3*CDIM*CDIM,
                                                     nullptr, nullptr, qkvh, NTOK, 3*CDIM, CDIM);
        if (d >= 9)
            mask_pre<<<NB, 256>>>(qkvh, maskb + (size_t)d*NB*NSEQ);
        attn_mma<<<NB*NHEAD, 256, ATT_SMEM>>>(qkvh, maskb + (size_t)d*NB*NSEQ, (d>=9)?1:0, oh);
        gemm_h<EP_BIAS_RES,float><<<dim3(6,99), 256>>>(oh, wh + W_PROJ + (size_t)d*CDIM*CDIM,
                                                       proj_b + d*CDIM, t, t, NTOK, CDIM, CDIM);
        ln_kernel<<<NTOK, 256>>>(t, ln2_w + d*CDIM, ln2_b + d*CDIM, ah);
        gemm_h<EP_BIAS_GELU,__half><<<dim3(24,99), 256>>>(ah, wh + W_FC1 + (size_t)d*4*CDIM*CDIM,
                                                          fc1_b + d*4*CDIM, nullptr, hh, NTOK, 4*CDIM, CDIM);
        gemm_h<EP_BIAS_RES,float><<<dim3(6,99), 256>>>(hh, wh + W_FC2 + (size_t)d*CDIM*4*CDIM,
                                                       fc2_b + d*CDIM, t, t, NTOK, CDIM, 4*CDIM);
    }

    ln_kernel<<<NTOK, 256>>>(t, norm_w, norm_b, ah);
    sfeat_kernel<<<(NB*CDIM+255)/256, 256>>>(ah, sfeat);
    head_kernel<<<(NB*200*32+255)/256, 256>>>(sfeat, head_w, head_b, out);
    final_mask<<<NB, 256>>>(maskb, gk, out);
}

// round 6
// speedup vs baseline: 6.1876x; 1.1378x over previous
#include <cuda_runtime.h>
#include <cuda_fp16.h>
#include <math.h>
#include <stdint.h>

// ---------------- problem constants ----------------
#define NB    64
#define NSEQ  198
#define NTOK  (NB*NSEQ)      // 12672 = 99*128
#define NPAT  (NB*196)       // 12544 = 98*128
#define CDIM  768
#define NHEAD 12
#define HD    64

// weight fp16 pool offsets
#define W_PATCH 0
#define W_QKV   589824
#define W_PROJ  21823488
#define W_FC1   28901376
#define W_FC2   57212928
#define W_TOTAL 85524480

// ---------------- scratch (device globals; no allocs allowed) ----------------
__device__ float  g_t   [(size_t)NTOK*CDIM];
__device__ float  g_o   [(size_t)NTOK*CDIM];
__device__ float  g_mask[(size_t)12*NB*NSEQ];
__device__ float  g_sfeat[(size_t)NB*6912];
__device__ __half g_ah  [(size_t)NTOK*CDIM];
__device__ __half g_qkvh[(size_t)NTOK*3*CDIM];
__device__ __half g_oh  [(size_t)NTOK*CDIM];
__device__ __half g_hh  [(size_t)NTOK*4*CDIM];
__device__ __half g_wh  [(size_t)W_TOTAL];

enum { EP_NONE=0, EP_BIAS=1, EP_BIAS_RES=2, EP_BIAS_GELU=3 };

// ---------------- helpers ----------------
__device__ __forceinline__ uint32_t smem_u32(const void* p){
    uint32_t a;
    asm("{ .reg .u64 t; cvta.to.shared.u64 t, %1; cvt.u32.u64 %0, t; }" : "=r"(a) : "l"(p));
    return a;
}
__device__ __forceinline__ void mma_fp16(float c[4], const unsigned a[4], const unsigned b[2]){
    asm volatile("mma.sync.aligned.m16n8k16.row.col.f32.f16.f16.f32 "
        "{%0,%1,%2,%3}, {%4,%5,%6,%7}, {%8,%9}, {%0,%1,%2,%3};\n"
        : "+f"(c[0]),"+f"(c[1]),"+f"(c[2]),"+f"(c[3])
        : "r"(a[0]),"r"(a[1]),"r"(a[2]),"r"(a[3]), "r"(b[0]),"r"(b[1]));
}
__device__ __forceinline__ void mma_fp16_k8(float c[4], const unsigned a[2], unsigned b0){
    asm volatile("mma.sync.aligned.m16n8k8.row.col.f32.f16.f16.f32 "
        "{%0,%1,%2,%3}, {%4,%5}, {%6}, {%0,%1,%2,%3};\n"
        : "+f"(c[0]),"+f"(c[1]),"+f"(c[2]),"+f"(c[3])
        : "r"(a[0]),"r"(a[1]), "r"(b0));
}
__device__ __forceinline__ void ldsm_x4(unsigned r[4], uint32_t a){
    asm volatile("ldmatrix.sync.aligned.m8n8.x4.shared.b16 {%0,%1,%2,%3}, [%4];"
        : "=r"(r[0]),"=r"(r[1]),"=r"(r[2]),"=r"(r[3]) : "r"(a));
}
__device__ __forceinline__ void cp16(uint32_t s, const void* g){
    asm volatile("cp.async.cg.shared.global [%0], [%1], 16;" :: "r"(s), "l"(g));
}
#define CP_COMMIT() asm volatile("cp.async.commit_group;" ::: "memory")
#define CP_WAIT(n)  asm volatile("cp.async.wait_group %0;" :: "n"(n) : "memory")

// ---------------- f32 -> f16 convert ----------------
__global__ void f2h_kernel(const float* __restrict__ src, __half* __restrict__ dst, int n4){
    int i = blockIdx.x*256 + threadIdx.x;
    if (i < n4){
        float4 v = ((const float4*)src)[i];
        ((__half2*)dst)[i*2  ] = __floats2half2_rn(v.x, v.y);
        ((__half2*)dst)[i*2+1] = __floats2half2_rn(v.z, v.w);
    }
}

// ---------------- pipelined fp16 GEMM-NT: C[M,N] = A[M,K]*B[N,K]^T ----------------
// 128x128x32 tile, 8 warps (warp tile 32x64), 4-stage cp.async, ldmatrix frags.
// stage layout: A 128 rows x 80B (10240) | B 128 rows x 80B (10240)
#define GSTAGES      4
#define GSTAGE_BYTES 20480
#define G_SMEM       (GSTAGES*GSTAGE_BYTES)   // 81920
template<int EPI, typename OT>
__global__ void __launch_bounds__(256) gemm_h2(
    const __half* __restrict__ A, const __half* __restrict__ B,
    const float* __restrict__ bias, const float* __restrict__ res,
    OT* __restrict__ C, int M, int N, int K)
{
    extern __shared__ char smem[];
    const uint32_t sb = smem_u32(smem);
    const int tid=threadIdx.x, warp=tid>>5, lane=tid&31;
    const int wm=warp>>1, wn=warp&1;
    const int gid=lane>>2, tg=lane&3;
    const int bm=blockIdx.y*128, bn=blockIdx.x*128;

    // cp.async mapping: thread -> rows (tid>>2, tid>>2 + 64), 16B seg (tid&3)
    const int lrow = tid>>2, lseg = tid&3;
    const __half* Ag = A + (size_t)(bm+lrow)*K + lseg*8;
    const __half* Bg = B + (size_t)(bn+lrow)*K + lseg*8;
    const uint32_t sOffA0 = (uint32_t)lrow*80 + lseg*16;
    const uint32_t sOffA1 = (uint32_t)(lrow+64)*80 + lseg*16;

    // ldmatrix fragment base addresses
    const uint32_t aBase = sb + (uint32_t)((wm*32 + (lane&15))*80 + (lane>>4)*16);
    const uint32_t bBase = sb + 10240u +
        (uint32_t)((wn*64 + (lane&7) + ((lane>>4)&1)*8)*80 + ((lane>>3)&1)*16);

    float acc[2][8][4];
#pragma unroll
    for(int i=0;i<2;i++)
#pragma unroll
        for(int j=0;j<8;j++)
#pragma unroll
            for(int q=0;q<4;q++) acc[i][j][q]=0.f;

    const int nit = K >> 5;

    // prologue: issue stages 0..2
#pragma unroll
    for (int s=0; s<3; s++){
        uint32_t st = sb + (uint32_t)s*GSTAGE_BYTES;
        size_t koff = (size_t)s*32;
        cp16(st + sOffA0,          Ag + koff);
        cp16(st + sOffA1,          Ag + (size_t)64*K + koff);
        cp16(st + 10240 + sOffA0,  Bg + koff);
        cp16(st + 10240 + sOffA1,  Bg + (size_t)64*K + koff);
        CP_COMMIT();
    }

    for (int it=0; it<nit; it++){
        if (it < nit-3)       CP_WAIT(2);
        else if (it == nit-2) CP_WAIT(1);
        else if (it == nit-1) CP_WAIT(0);
        else                  CP_WAIT(2);   // it == nit-3
        __syncthreads();
        if (it + 3 < nit){
            int ss = (it+3) & 3;
            uint32_t st = sb + (uint32_t)ss*GSTAGE_BYTES;
            size_t koff = (size_t)(it+3)*32;
            cp16(st + sOffA0,          Ag + koff);
            cp16(st + sOffA1,          Ag + (size_t)64*K + koff);
            cp16(st + 10240 + sOffA0,  Bg + koff);
            cp16(st + 10240 + sOffA1,  Bg + (size_t)64*K + koff);
            CP_COMMIT();
        }
        const uint32_t stoff = (uint32_t)(it & 3)*GSTAGE_BYTES;
#pragma unroll
        for (int ks=0; ks<2; ks++){
            unsigned af0[4], af1[4];
            ldsm_x4(af0, aBase + stoff + ks*32);
            ldsm_x4(af1, aBase + stoff + 1280 + ks*32);
#pragma unroll
            for (int jp=0; jp<4; jp++){
                unsigned bf[4];
                ldsm_x4(bf, bBase + stoff + (uint32_t)jp*1280 + ks*32);
                mma_fp16(acc[0][2*jp  ], af0, bf);
                mma_fp16(acc[0][2*jp+1], af0, bf+2);
                mma_fp16(acc[1][2*jp  ], af1, bf);
                mma_fp16(acc[1][2*jp+1], af1, bf+2);
            }
        }
    }

#pragma unroll
    for(int i=0;i<2;i++){
#pragma unroll
        for(int rr=0;rr<2;rr++){
            int row = bm + wm*32 + i*16 + gid + rr*8;
#pragma unroll
            for(int j=0;j<8;j++){
                int col = bn + wn*64 + j*8 + tg*2;
                float v0 = acc[i][j][rr*2+0];
                float v1 = acc[i][j][rr*2+1];
                if (EPI == EP_BIAS) { v0 += bias[col]; v1 += bias[col+1]; }
                else if (EPI == EP_BIAS_RES) {
                    v0 += bias[col]   + res[(size_t)row*N+col];
                    v1 += bias[col+1] + res[(size_t)row*N+col+1];
                }
                else if (EPI == EP_BIAS_GELU) {
                    v0 += bias[col];   v1 += bias[col+1];
                    v0 = 0.5f*v0*(1.f + erff(v0*0.70710678118654752f));
                    v1 = 0.5f*v1*(1.f + erff(v1*0.70710678118654752f));
                }
                if (sizeof(OT)==2) {
                    *(__half2*)((__half*)C + (size_t)row*N + col) = __floats2half2_rn(v0, v1);
                } else {
                    *(float2*)((float*)C + (size_t)row*N + col) = make_float2(v0, v1);
                }
            }
        }
    }
}

// ---------------- patch im2col -> fp16 ----------------
__global__ void im2col_patch(const float* __restrict__ x, __half* __restrict__ A)
{
    int i = blockIdx.x*256 + threadIdx.x;
    if (i >= NPAT*CDIM) return;
    int p = i / CDIM, kidx = i - p*CDIM;
    int b = p / 196, pp = p - b*196;
    int py = pp / 14, px = pp - py*14;
    int c = kidx >> 8;
    int rem = kidx & 255;
    int iy = rem >> 4, ix = rem & 15;
    A[i] = __float2half(x[(((size_t)b*3 + c)*224 + (py*16+iy))*224 + (px*16+ix)]);
}

// ---------------- assemble token stream ----------------
__global__ void assemble_t(const float* __restrict__ P, const float* __restrict__ cls,
                           const float* __restrict__ loc, const float* __restrict__ pos,
                           const float* __restrict__ loce, float* __restrict__ T)
{
    int i = blockIdx.x*256 + threadIdx.x;
    if (i >= NTOK*CDIM) return;
    int tok = i / CDIM, c = i - tok*CDIM;
    int b = tok / NSEQ, tt = tok - b*NSEQ;
    float v;
    if (tt == 0)          v = cls[c] + pos[c];
    else if (tt == 197)   v = loc[c] + loce[c];
    else                  v = P[((size_t)b*196 + tt-1)*CDIM + c] + pos[(size_t)tt*CDIM + c];
    T[i] = v;
}

// ---------------- layernorm: fp32 in, fp16 out ----------------
__launch_bounds__(256)
__global__ void ln_kernel(const float* __restrict__ X, const float* __restrict__ w,
                          const float* __restrict__ bb, __half* __restrict__ Y)
{
    int row = blockIdx.x;
    const float* x = X + (size_t)row * CDIM;
    __half* y = Y + (size_t)row * CDIM;
    int tid = threadIdx.x;
    float v0 = x[tid], v1 = x[tid+256], v2 = x[tid+512];
    __shared__ float red[8];
    __shared__ float mrs[2];
    float s = v0+v1+v2;
#pragma unroll
    for (int o=16;o;o>>=1) s += __shfl_xor_sync(0xffffffffu, s, o);
    if ((tid&31)==0) red[tid>>5] = s;
    __syncthreads();
    if (tid==0){ float t=0.f; for(int i=0;i<8;i++) t+=red[i]; mrs[0]=t*(1.f/768.f); }
    __syncthreads();
    float m = mrs[0];
    float d0=v0-m, d1=v1-m, d2=v2-m;
    float q = d0*d0+d1*d1+d2*d2;
#pragma unroll
    for (int o=16;o;o>>=1) q += __shfl_xor_sync(0xffffffffu, q, o);
    __syncthreads();
    if ((tid&31)==0) red[tid>>5] = q;
    __syncthreads();
    if (tid==0){ float t=0.f; for(int i=0;i<8;i++) t+=red[i]; mrs[1]=rsqrtf(t*(1.f/768.f)+1e-5f); }
    __syncthreads();
    float rs = mrs[1];
    y[tid]     = __float2half(d0*rs*w[tid]     + bb[tid]);
    y[tid+256] = __float2half(d1*rs*w[tid+256] + bb[tid+256]);
    y[tid+512] = __float2half(d2*rs*w[tid+512] + bb[tid+512]);
}

// ---------------- mask precompute (fp16 qkv) ----------------
__launch_bounds__(256)
__global__ void mask_pre(const __half* __restrict__ qkv, float* __restrict__ mask)
{
    int b = blockIdx.x;
    __shared__ float q197[CDIM];
    int tid = threadIdx.x;
    const __half* qrow = qkv + ((size_t)b*NSEQ + 197)*(3*CDIM);
    for (int i=tid;i<CDIM;i+=256) q197[i]=__half2float(qrow[i]);
    __syncthreads();
    int warp=tid>>5, lane=tid&31;
    for (int k=warp; k<NSEQ; k+=8){
        const __half* krow = qkv + ((size_t)b*NSEQ + k)*(3*CDIM) + CDIM;
        float s=0.f;
        for (int d=lane; d<CDIM; d+=32) s = fmaf(q197[d], __half2float(krow[d]), s);
#pragma unroll
        for (int o=16;o;o>>=1) s += __shfl_xor_sync(0xffffffffu, s, o);
        if (lane==0) mask[(size_t)b*NSEQ + k] = 1.f/(1.f + __expf(-s*(0.125f/12.f)));
    }
}

// ---------------- fused mma.sync attention per (b,h) ----------------
#define ATT_SMEM (166400 + 29952 + 29952)
__global__ void __launch_bounds__(256) attn_mma(
    const __half* __restrict__ qkv, const float* __restrict__ mask,
    int use_mask, __half* __restrict__ O)
{
    int bh = blockIdx.x;
    int b = bh / NHEAD, h = bh - b*NHEAD;
    extern __shared__ char smem[];
    float*  Ss = (float*)smem;
    __half* Qs = (__half*)(smem + 166400);
    __half* Ks = (__half*)(smem + 166400+29952);
    const int tid=threadIdx.x, warp=tid>>5, lane=tid&31;
    const int gid=lane>>2, tg=lane&3;
    const __half* base = qkv + (size_t)b*NSEQ*(3*CDIM) + h*HD;
    const __half hz = __float2half(0.f);

    for (int i = tid; i < 208*64; i += 256){
        int t = i>>6, d = i&63;
        __half q = hz, k = hz;
        if (t < NSEQ){
            q = base[(size_t)t*(3*CDIM) + d];
            k = base[(size_t)t*(3*CDIM) + CDIM + d];
        }
        Qs[t*72+d] = q; Ks[t*72+d] = k;
    }
    __syncthreads();

    for (int mt = warp; mt < 13; mt += 8){
        int m0 = mt*16;
        unsigned af[4][4];
#pragma unroll
        for (int ks=0; ks<4; ks++){
            int kb = ks*16 + 2*tg;
            af[ks][0] = *(const unsigned*)&Qs[(m0+gid  )*72 + kb  ];
            af[ks][1] = *(const unsigned*)&Qs[(m0+gid+8)*72 + kb  ];
            af[ks][2] = *(const unsigned*)&Qs[(m0+gid  )*72 + kb+8];
            af[ks][3] = *(const unsigned*)&Qs[(m0+gid+8)*72 + kb+8];
        }
        for (int nt = 0; nt < 25; nt++){
            int n0 = nt*8;
            float acc[4] = {0.f,0.f,0.f,0.f};
#pragma unroll
            for (int ks=0; ks<4; ks++){
                int kb = ks*16 + 2*tg;
                unsigned bb[2];
                bb[0] = *(const unsigned*)&Ks[(n0+gid)*72 + kb  ];
                bb[1] = *(const unsigned*)&Ks[(n0+gid)*72 + kb+8];
                mma_fp16(acc, af[ks], bb);
            }
            int r = m0 + gid, c = n0 + tg*2;
            Ss[(size_t)r*200 + c  ] = acc[0]*0.125f;
            Ss[(size_t)r*200 + c+1] = acc[1]*0.125f;
            Ss[(size_t)(r+8)*200 + c  ] = acc[2]*0.125f;
            Ss[(size_t)(r+8)*200 + c+1] = acc[3]*0.125f;
        }
    }
    __syncthreads();

    __half* Vs = Qs;
    for (int i = tid; i < 64*216; i += 256){
        int d = i/216, k = i - d*216;
        __half v = hz;
        if (k < NSEQ) v = base[(size_t)k*(3*CDIM) + 2*CDIM + d];
        Vs[d*216 + k] = v;
    }
    const float* mrow = mask + (size_t)b*NSEQ;
    for (int row = warp; row < NSEQ; row += 8){
        float* Sr = Ss + (size_t)row*200;
        float v[7]; float mx = -1e30f;
#pragma unroll
        for (int j=0;j<7;j++){
            int col = lane + 32*j;
            v[j] = (col < NSEQ) ? Sr[col] : -1e30f;
            mx = fmaxf(mx, v[j]);
        }
#pragma unroll
        for (int o=16;o;o>>=1) mx = fmaxf(mx, __shfl_xor_sync(0xffffffffu, mx, o));
        float sum = 0.f;
#pragma unroll
        for (int j=0;j<7;j++){
            int col = lane + 32*j;
            v[j] = (col < NSEQ) ? __expf(v[j]-mx) : 0.f;
            sum += v[j];
        }
#pragma unroll
        for (int o=16;o;o>>=1) sum += __shfl_xor_sync(0xffffffffu, sum, o);
        float inv = 1.f/sum;
#pragma unroll
        for (int j=0;j<7;j++){
            int col = lane + 32*j;
            if (col < NSEQ){
                float p = v[j]*inv;
                if (use_mask) p *= mrow[col];
                Sr[col] = p;
            }
        }
        if (lane < 2) Sr[NSEQ + lane] = 0.f;
    }
    __syncthreads();

    __half* Oh = O + (size_t)b*NSEQ*CDIM + h*HD;
    for (int mt = warp; mt < 13; mt += 8){
        int m0 = mt*16;
        float acc[8][4];
#pragma unroll
        for (int j=0;j<8;j++)
#pragma unroll
            for (int q=0;q<4;q++) acc[j][q]=0.f;
        for (int ks = 0; ks < 12; ks++){
            int k0 = ks*16 + 2*tg;
            unsigned af[4];
            {
                float2 p0 = *(const float2*)&Ss[(size_t)(m0+gid  )*200 + k0  ];
                float2 p1 = *(const float2*)&Ss[(size_t)(m0+gid+8)*200 + k0  ];
                float2 p2 = *(const float2*)&Ss[(size_t)(m0+gid  )*200 + k0+8];
                float2 p3 = *(const float2*)&Ss[(size_t)(m0+gid+8)*200 + k0+8];
                __half2 h0=__floats2half2_rn(p0.x,p0.y), h1=__floats2half2_rn(p1.x,p1.y);
                __half2 h2=__floats2half2_rn(p2.x,p2.y), h3=__floats2half2_rn(p3.x,p3.y);
                af[0]=*(unsigned*)&h0; af[1]=*(unsigned*)&h1;
                af[2]=*(unsigned*)&h2; af[3]=*(unsigned*)&h3;
            }
#pragma unroll
            for (int nt = 0; nt < 8; nt++){
                unsigned bb[2];
                bb[0] = *(const unsigned*)&Vs[(nt*8+gid)*216 + k0  ];
                bb[1] = *(const unsigned*)&Vs[(nt*8+gid)*216 + k0+8];
                mma_fp16(acc[nt], af, bb);
            }
        }
        {
            int k0 = 192 + 2*tg;
            float2 p0 = *(const float2*)&Ss[(size_t)(m0+gid  )*200 + k0];
            float2 p1 = *(const float2*)&Ss[(size_t)(m0+gid+8)*200 + k0];
            __half2 h0=__floats2half2_rn(p0.x,p0.y), h1=__floats2half2_rn(p1.x,p1.y);
            unsigned af2[2]; af2[0]=*(unsigned*)&h0; af2[1]=*(unsigned*)&h1;
#pragma unroll
            for (int nt = 0; nt < 8; nt++){
                unsigned b0 = *(const unsigned*)&Vs[(nt*8+gid)*216 + k0];
                mma_fp16_k8(acc[nt], af2, b0);
            }
        }
#pragma unroll
        for (int rr = 0; rr < 2; rr++){
            int q = m0 + gid + rr*8;
            if (q < NSEQ){
#pragma unroll
                for (int nt = 0; nt < 8; nt++){
                    *(__half2*)&Oh[(size_t)q*CDIM + nt*8 + tg*2] =
                        __floats2half2_rn(acc[nt][rr*2], acc[nt][rr*2+1]);
                }
            }
        }
    }
}

// ---------------- head features: 9 rectangle sums per (b,c) ----------------
__launch_bounds__(256)
__global__ void sfeat_kernel(const __half* __restrict__ T, float* __restrict__ SF)
{
    int i = blockIdx.x*256 + threadIdx.x;
    if (i >= NB*CDIM) return;
    int b = i / CDIM, c = i - b*CDIM;
    const __half* base = T + ((size_t)b*NSEQ + 1)*CDIM + c;
    float tot=0.f, r0=0.f, r13=0.f, c0s=0.f, c13s=0.f;
    for (int u=0; u<14; u++) {
        for (int v=0; v<14; v++) {
            float val = __half2float(base[(size_t)(u*14+v)*CDIM]);
            tot += val;
            if (u==0)  r0  += val;
            if (u==13) r13 += val;
            if (v==0)  c0s += val;
            if (v==13) c13s += val;
        }
    }
    float x00 = __half2float(base[0]);
    float x0e = __half2float(base[(size_t)13*CDIM]);
    float xe0 = __half2float(base[(size_t)(13*14)*CDIM]);
    float xee = __half2float(base[(size_t)(13*14+13)*CDIM]);
    float* o = SF + (size_t)b*6912 + c*9;
    for (int dy=0; dy<3; dy++)
        for (int dx=0; dx<3; dx++) {
            float s = tot;
            if (dy==0) s -= r13;
            if (dy==2) s -= r0;
            if (dx==0) s -= c13s;
            if (dx==2) s -= c0s;
            if (dy==0 && dx==0) s += xee;
            if (dy==0 && dx==2) s += xe0;
            if (dy==2 && dx==0) s += x0e;
            if (dy==2 && dx==2) s += x00;
            o[dy*3+dx] = s;
        }
}

// ---------------- logits ----------------
__launch_bounds__(256)
__global__ void head_kernel(const float* __restrict__ SF, const float* __restrict__ W,
                            const float* __restrict__ bias, float* __restrict__ out)
{
    int gw = (blockIdx.x*256 + threadIdx.x) >> 5;
    int lane = threadIdx.x & 31;
    if (gw >= NB*200) return;
    int b = gw / 200, cls = gw - b*200;
    const float* a = SF + (size_t)b*6912;
    const float* w = W + (size_t)cls*6912;
    float s = 0.f;
    for (int k = lane; k < 6912; k += 32) s = fmaf(a[k], w[k], s);
#pragma unroll
    for (int o=16;o;o>>=1) s += __shfl_xor_sync(0xffffffffu, s, o);
    if (lane==0) out[gw] = s*(1.f/196.f) + bias[cls];
}

// ---------------- final mask outputs ----------------
__launch_bounds__(256)
__global__ void final_mask(const float* __restrict__ Mlayers, const float* __restrict__ gk,
                           float* __restrict__ out)
{
    int b = blockIdx.x;
    __shared__ float ma[196];
    __shared__ float red[8];
    int tid = threadIdx.x;
    if (tid < 196) {
        float s = 0.f;
        for (int l=9; l<12; l++) s += Mlayers[((size_t)l*NB + b)*NSEQ + 1 + tid];
        ma[tid] = s * (1.f/3.f);
    }
    __syncthreads();
    float part = (tid < 196) ? ma[tid] : 0.f;
#pragma unroll
    for (int o=16;o;o>>=1) part += __shfl_xor_sync(0xffffffffu, part, o);
    if ((tid&31)==0) red[tid>>5] = part;
    __syncthreads();
    if (tid==0){ float t=0.f; for(int i=0;i<8;i++) t+=red[i]; out[12800 + b] = t*(1.f/196.f); }
    float t3 = 0.f;
    if (tid < 196) {
        int y = tid/14, x = tid - y*14;
        float m = 0.f;
        for (int dy=0; dy<3; dy++)
            for (int dx=0; dx<3; dx++) {
                int yy = y+dy-1, xx = x+dx-1;
                if (yy>=0 && yy<14 && xx>=0 && xx<14)
                    m += gk[dy*3+dx]*ma[yy*14+xx];
            }
        t3 = (1.f - m)*m;
    }
    __syncthreads();
#pragma unroll
    for (int o=16;o;o>>=1) t3 += __shfl_xor_sync(0xffffffffu, t3, o);
    if ((tid&31)==0) red[tid>>5] = t3;
    __syncthreads();
    if (tid==0){ float t=0.f; for(int i=0;i<8;i++) t+=red[i]; out[12864 + b] = t*(1.f/196.f); }
}

// ---------------- launch ----------------
extern "C" void kernel_launch(void* const* d_in, const int* in_sizes, int n_in,
                              void* d_out, int out_size)
{
    const float* x       = (const float*)d_in[0];
    const float* patch_w = (const float*)d_in[1];
    const float* patch_b = (const float*)d_in[2];
    const float* cls_tok = (const float*)d_in[3];
    const float* loc_tok = (const float*)d_in[4];
    const float* pos_emb = (const float*)d_in[5];
    const float* loc_emb = (const float*)d_in[6];
    const float* ln1_w   = (const float*)d_in[7];
    const float* ln1_b   = (const float*)d_in[8];
    const float* qkv_w   = (const float*)d_in[9];
    const float* proj_w  = (const float*)d_in[10];
    const float* proj_b  = (const float*)d_in[11];
    const float* ln2_w   = (const float*)d_in[12];
    const float* ln2_b   = (const float*)d_in[13];
    const float* fc1_w   = (const float*)d_in[14];
    const float* fc1_b   = (const float*)d_in[15];
    const float* fc2_w   = (const float*)d_in[16];
    const float* fc2_b   = (const float*)d_in[17];
    const float* norm_w  = (const float*)d_in[18];
    const float* norm_b  = (const float*)d_in[19];
    const float* head_w  = (const float*)d_in[20];
    const float* head_b  = (const float*)d_in[21];
    const float* gk      = (const float*)d_in[22];
    float* out = (float*)d_out;

    float *t, *o, *maskb, *sfeat;
    __half *ah, *qkvh, *oh, *hh, *wh;
    cudaGetSymbolAddress((void**)&t,     g_t);
    cudaGetSymbolAddress((void**)&o,     g_o);
    cudaGetSymbolAddress((void**)&maskb, g_mask);
    cudaGetSymbolAddress((void**)&sfeat, g_sfeat);
    cudaGetSymbolAddress((void**)&ah,    g_ah);
    cudaGetSymbolAddress((void**)&qkvh,  g_qkvh);
    cudaGetSymbolAddress((void**)&oh,    g_oh);
    cudaGetSymbolAddress((void**)&hh,    g_hh);
    cudaGetSymbolAddress((void**)&wh,    g_wh);

    cudaFuncSetAttribute(attn_mma, cudaFuncAttributeMaxDynamicSharedMemorySize, ATT_SMEM);
    cudaFuncSetAttribute(gemm_h2<EP_BIAS,float>,       cudaFuncAttributeMaxDynamicSharedMemorySize, G_SMEM);
    cudaFuncSetAttribute(gemm_h2<EP_NONE,__half>,      cudaFuncAttributeMaxDynamicSharedMemorySize, G_SMEM);
    cudaFuncSetAttribute(gemm_h2<EP_BIAS_RES,float>,   cudaFuncAttributeMaxDynamicSharedMemorySize, G_SMEM);
    cudaFuncSetAttribute(gemm_h2<EP_BIAS_GELU,__half>, cudaFuncAttributeMaxDynamicSharedMemorySize, G_SMEM);

    // convert weights to fp16 pool (must run every call; inputs may change)
    f2h_kernel<<<(589824/4+255)/256,   256>>>(patch_w, wh + W_PATCH, 589824/4);
    f2h_kernel<<<(21233664/4+255)/256, 256>>>(qkv_w,   wh + W_QKV,   21233664/4);
    f2h_kernel<<<(7077888/4+255)/256,  256>>>(proj_w,  wh + W_PROJ,  7077888/4);
    f2h_kernel<<<(28311552/4+255)/256, 256>>>(fc1_w,   wh + W_FC1,   28311552/4);
    f2h_kernel<<<(28311552/4+255)/256, 256>>>(fc2_w,   wh + W_FC2,   28311552/4);

    // patch embed
    im2col_patch<<<(NPAT*CDIM+255)/256, 256>>>(x, ah);
    gemm_h2<EP_BIAS,float><<<dim3(6,98), 256, G_SMEM>>>(ah, wh + W_PATCH, patch_b, nullptr, o, NPAT, CDIM, CDIM);
    assemble_t<<<(NTOK*CDIM+255)/256, 256>>>(o, cls_tok, loc_tok, pos_emb, loc_emb, t);

    for (int d=0; d<12; d++) {
        ln_kernel<<<NTOK, 256>>>(t, ln1_w + d*CDIM, ln1_b + d*CDIM, ah);
        gemm_h2<EP_NONE,__half><<<dim3(18,99), 256, G_SMEM>>>(ah, wh + W_QKV + (size_t)d*3*CDIM*CDIM,
                                                              nullptr, nullptr, qkvh, NTOK, 3*CDIM, CDIM);
        if (d >= 9)
            mask_pre<<<NB, 256>>>(qkvh, maskb + (size_t)d*NB*NSEQ);
        attn_mma<<<NB*NHEAD, 256, ATT_SMEM>>>(qkvh, maskb + (size_t)d*NB*NSEQ, (d>=9)?1:0, oh);
        gemm_h2<EP_BIAS_RES,float><<<dim3(6,99), 256, G_SMEM>>>(oh, wh + W_PROJ + (size_t)d*CDIM*CDIM,
                                                                proj_b + d*CDIM, t, t, NTOK, CDIM, CDIM);
        ln_kernel<<<NTOK, 256>>>(t, ln2_w + d*CDIM, ln2_b + d*CDIM, ah);
        gemm_h2<EP_BIAS_GELU,__half><<<dim3(24,99), 256, G_SMEM>>>(ah, wh + W_FC1 + (size_t)d*4*CDIM*CDIM,
                                                                   fc1_b + d*4*CDIM, nullptr, hh, NTOK, 4*CDIM, CDIM);
        gemm_h2<EP_BIAS_RES,float><<<dim3(6,99), 256, G_SMEM>>>(hh, wh + W_FC2 + (size_t)d*CDIM*4*CDIM,
                                                                fc2_b + d*CDIM, t, t, NTOK, CDIM, 4*CDIM);
    }

    ln_kernel<<<NTOK, 256>>>(t, norm_w, norm_b, ah);
    sfeat_kernel<<<(NB*CDIM+255)/256, 256>>>(ah, sfeat);
    head_kernel<<<(NB*200*32+255)/256, 256>>>(sfeat, head_w, head_b, out);
    final_mask<<<NB, 256>>>(maskb, gk, out);
}

// round 7
// speedup vs baseline: 6.5170x; 1.0532x over previous
#include <cuda_runtime.h>
#include <cuda_fp16.h>
#include <math.h>
#include <stdint.h>

// ---------------- problem constants ----------------
#define NB    64
#define NSEQ  198
#define NTOK  (NB*NSEQ)      // 12672 = 99*128
#define NPAT  (NB*196)       // 12544 = 98*128
#define CDIM  768
#define NHEAD 12
#define HD    64

// weight fp16 pool offsets
#define W_PATCH 0
#define W_QKV   589824
#define W_PROJ  21823488
#define W_FC1   28901376
#define W_FC2   57212928
#define W_TOTAL 85524480

// ---------------- scratch (device globals; no allocs allowed) ----------------
__device__ float  g_t   [(size_t)NTOK*CDIM];
__device__ float  g_o   [(size_t)NTOK*CDIM];
__device__ float  g_mask[(size_t)12*NB*NSEQ];
__device__ float  g_sfeat[(size_t)NB*6912];
__device__ __half g_ah  [(size_t)NTOK*CDIM];
__device__ __half g_qkvh[(size_t)NTOK*3*CDIM];
__device__ __half g_oh  [(size_t)NTOK*CDIM];
__device__ __half g_hh  [(size_t)NTOK*4*CDIM];
__device__ __half g_wh  [(size_t)W_TOTAL];

enum { EP_NONE=0, EP_BIAS=1, EP_BIAS_RES=2, EP_BIAS_GELU=3 };

// ---------------- helpers ----------------
__device__ __forceinline__ uint32_t smem_u32(const void* p){
    uint32_t a;
    asm("{ .reg .u64 t; cvta.to.shared.u64 t, %1; cvt.u32.u64 %0, t; }" : "=r"(a) : "l"(p));
    return a;
}
__device__ __forceinline__ void mma_fp16(float c[4], const unsigned a[4], const unsigned b[2]){
    asm volatile("mma.sync.aligned.m16n8k16.row.col.f32.f16.f16.f32 "
        "{%0,%1,%2,%3}, {%4,%5,%6,%7}, {%8,%9}, {%0,%1,%2,%3};\n"
        : "+f"(c[0]),"+f"(c[1]),"+f"(c[2]),"+f"(c[3])
        : "r"(a[0]),"r"(a[1]),"r"(a[2]),"r"(a[3]), "r"(b[0]),"r"(b[1]));
}
__device__ __forceinline__ void mma_fp16_k8(float c[4], const unsigned a[2], unsigned b0){
    asm volatile("mma.sync.aligned.m16n8k8.row.col.f32.f16.f16.f32 "
        "{%0,%1,%2,%3}, {%4,%5}, {%6}, {%0,%1,%2,%3};\n"
        : "+f"(c[0]),"+f"(c[1]),"+f"(c[2]),"+f"(c[3])
        : "r"(a[0]),"r"(a[1]), "r"(b0));
}
__device__ __forceinline__ void ldsm_x4(unsigned r[4], uint32_t a){
    asm volatile("ldmatrix.sync.aligned.m8n8.x4.shared.b16 {%0,%1,%2,%3}, [%4];"
        : "=r"(r[0]),"=r"(r[1]),"=r"(r[2]),"=r"(r[3]) : "r"(a));
}
__device__ __forceinline__ void cp16(uint32_t s, const void* g){
    asm volatile("cp.async.cg.shared.global [%0], [%1], 16;" :: "r"(s), "l"(g));
}
#define CP_COMMIT() asm volatile("cp.async.commit_group;" ::: "memory")
#define CP_WAIT(n)  asm volatile("cp.async.wait_group %0;" :: "n"(n) : "memory")

// ---------------- f32 -> f16 convert ----------------
__global__ void f2h_kernel(const float* __restrict__ src, __half* __restrict__ dst, int n4){
    int i = blockIdx.x*256 + threadIdx.x;
    if (i < n4){
        float4 v = ((const float4*)src)[i];
        ((__half2*)dst)[i*2  ] = __floats2half2_rn(v.x, v.y);
        ((__half2*)dst)[i*2+1] = __floats2half2_rn(v.z, v.w);
    }
}

// ---------------- pipelined fp16 GEMM-NT: C[M,N] = A[M,K]*B[N,K]^T ----------------
#define GSTAGES      4
#define GSTAGE_BYTES 20480
#define G_SMEM       (GSTAGES*GSTAGE_BYTES)   // 81920
template<int EPI, typename OT>
__global__ void __launch_bounds__(256,2) gemm_h2(
    const __half* __restrict__ A, const __half* __restrict__ B,
    const float* __restrict__ bias, const float* __restrict__ res,
    OT* __restrict__ C, int M, int N, int K)
{
    extern __shared__ char smem[];
    const uint32_t sb = smem_u32(smem);
    const int tid=threadIdx.x, warp=tid>>5, lane=tid&31;
    const int wm=warp>>1, wn=warp&1;
    const int gid=lane>>2, tg=lane&3;
    const int bm=blockIdx.y*128, bn=blockIdx.x*128;

    const int lrow = tid>>2, lseg = tid&3;
    const __half* Ag = A + (size_t)(bm+lrow)*K + lseg*8;
    const __half* Bg = B + (size_t)(bn+lrow)*K + lseg*8;
    const uint32_t sOffA0 = (uint32_t)lrow*80 + lseg*16;
    const uint32_t sOffA1 = (uint32_t)(lrow+64)*80 + lseg*16;

    const uint32_t aBase = sb + (uint32_t)((wm*32 + (lane&15))*80 + (lane>>4)*16);
    const uint32_t bBase = sb + 10240u +
        (uint32_t)((wn*64 + (lane&7) + ((lane>>4)&1)*8)*80 + ((lane>>3)&1)*16);

    float acc[2][8][4];
#pragma unroll
    for(int i=0;i<2;i++)
#pragma unroll
        for(int j=0;j<8;j++)
#pragma unroll
            for(int q=0;q<4;q++) acc[i][j][q]=0.f;

    const int nit = K >> 5;

#pragma unroll
    for (int s=0; s<3; s++){
        uint32_t st = sb + (uint32_t)s*GSTAGE_BYTES;
        size_t koff = (size_t)s*32;
        cp16(st + sOffA0,          Ag + koff);
        cp16(st + sOffA1,          Ag + (size_t)64*K + koff);
        cp16(st + 10240 + sOffA0,  Bg + koff);
        cp16(st + 10240 + sOffA1,  Bg + (size_t)64*K + koff);
        CP_COMMIT();
    }

    for (int it=0; it<nit; it++){
        if (it < nit-3)       CP_WAIT(2);
        else if (it == nit-2) CP_WAIT(1);
        else if (it == nit-1) CP_WAIT(0);
        else                  CP_WAIT(2);
        __syncthreads();
        if (it + 3 < nit){
            int ss = (it+3) & 3;
            uint32_t st = sb + (uint32_t)ss*GSTAGE_BYTES;
            size_t koff = (size_t)(it+3)*32;
            cp16(st + sOffA0,          Ag + koff);
            cp16(st + sOffA1,          Ag + (size_t)64*K + koff);
            cp16(st + 10240 + sOffA0,  Bg + koff);
            cp16(st + 10240 + sOffA1,  Bg + (size_t)64*K + koff);
            CP_COMMIT();
        }
        const uint32_t stoff = (uint32_t)(it & 3)*GSTAGE_BYTES;
#pragma unroll
        for (int ks=0; ks<2; ks++){
            unsigned af0[4], af1[4];
            ldsm_x4(af0, aBase + stoff + ks*32);
            ldsm_x4(af1, aBase + stoff + 1280 + ks*32);
#pragma unroll
            for (int jp=0; jp<4; jp++){
                unsigned bf[4];
                ldsm_x4(bf, bBase + stoff + (uint32_t)jp*1280 + ks*32);
                mma_fp16(acc[0][2*jp  ], af0, bf);
                mma_fp16(acc[0][2*jp+1], af0, bf+2);
                mma_fp16(acc[1][2*jp  ], af1, bf);
                mma_fp16(acc[1][2*jp+1], af1, bf+2);
            }
        }
    }

#pragma unroll
    for(int i=0;i<2;i++){
#pragma unroll
        for(int rr=0;rr<2;rr++){
            int row = bm + wm*32 + i*16 + gid + rr*8;
#pragma unroll
            for(int j=0;j<8;j++){
                int col = bn + wn*64 + j*8 + tg*2;
                float v0 = acc[i][j][rr*2+0];
                float v1 = acc[i][j][rr*2+1];
                if (EPI == EP_BIAS) { v0 += bias[col]; v1 += bias[col+1]; }
                else if (EPI == EP_BIAS_RES) {
                    v0 += bias[col]   + res[(size_t)row*N+col];
                    v1 += bias[col+1] + res[(size_t)row*N+col+1];
                }
                else if (EPI == EP_BIAS_GELU) {
                    v0 += bias[col];   v1 += bias[col+1];
                    v0 = 0.5f*v0*(1.f + erff(v0*0.70710678118654752f));
                    v1 = 0.5f*v1*(1.f + erff(v1*0.70710678118654752f));
                }
                if (sizeof(OT)==2) {
                    *(__half2*)((__half*)C + (size_t)row*N + col) = __floats2half2_rn(v0, v1);
                } else {
                    *(float2*)((float*)C + (size_t)row*N + col) = make_float2(v0, v1);
                }
            }
        }
    }
}

// ---------------- patch im2col -> fp16 ----------------
__global__ void im2col_patch(const float* __restrict__ x, __half* __restrict__ A)
{
    int i = blockIdx.x*256 + threadIdx.x;
    if (i >= NPAT*CDIM) return;
    int p = i / CDIM, kidx = i - p*CDIM;
    int b = p / 196, pp = p - b*196;
    int py = pp / 14, px = pp - py*14;
    int c = kidx >> 8;
    int rem = kidx & 255;
    int iy = rem >> 4, ix = rem & 15;
    A[i] = __float2half(x[(((size_t)b*3 + c)*224 + (py*16+iy))*224 + (px*16+ix)]);
}

// ---------------- assemble token stream ----------------
__global__ void assemble_t(const float* __restrict__ P, const float* __restrict__ cls,
                           const float* __restrict__ loc, const float* __restrict__ pos,
                           const float* __restrict__ loce, float* __restrict__ T)
{
    int i = blockIdx.x*256 + threadIdx.x;
    if (i >= NTOK*CDIM) return;
    int tok = i / CDIM, c = i - tok*CDIM;
    int b = tok / NSEQ, tt = tok - b*NSEQ;
    float v;
    if (tt == 0)          v = cls[c] + pos[c];
    else if (tt == 197)   v = loc[c] + loce[c];
    else                  v = P[((size_t)b*196 + tt-1)*CDIM + c] + pos[(size_t)tt*CDIM + c];
    T[i] = v;
}

// ---------------- layernorm: fp32 in, fp16 out ----------------
__launch_bounds__(256)
__global__ void ln_kernel(const float* __restrict__ X, const float* __restrict__ w,
                          const float* __restrict__ bb, __half* __restrict__ Y)
{
    int row = blockIdx.x;
    const float* x = X + (size_t)row * CDIM;
    __half* y = Y + (size_t)row * CDIM;
    int tid = threadIdx.x;
    float v0 = x[tid], v1 = x[tid+256], v2 = x[tid+512];
    __shared__ float red[8];
    __shared__ float mrs[2];
    float s = v0+v1+v2;
#pragma unroll
    for (int o=16;o;o>>=1) s += __shfl_xor_sync(0xffffffffu, s, o);
    if ((tid&31)==0) red[tid>>5] = s;
    __syncthreads();
    if (tid==0){ float t=0.f; for(int i=0;i<8;i++) t+=red[i]; mrs[0]=t*(1.f/768.f); }
    __syncthreads();
    float m = mrs[0];
    float d0=v0-m, d1=v1-m, d2=v2-m;
    float q = d0*d0+d1*d1+d2*d2;
#pragma unroll
    for (int o=16;o;o>>=1) q += __shfl_xor_sync(0xffffffffu, q, o);
    __syncthreads();
    if ((tid&31)==0) red[tid>>5] = q;
    __syncthreads();
    if (tid==0){ float t=0.f; for(int i=0;i<8;i++) t+=red[i]; mrs[1]=rsqrtf(t*(1.f/768.f)+1e-5f); }
    __syncthreads();
    float rs = mrs[1];
    y[tid]     = __float2half(d0*rs*w[tid]     + bb[tid]);
    y[tid+256] = __float2half(d1*rs*w[tid+256] + bb[tid+256]);
    y[tid+512] = __float2half(d2*rs*w[tid+512] + bb[tid+512]);
}

// ---------------- mask precompute (fp16 qkv) ----------------
__launch_bounds__(256)
__global__ void mask_pre(const __half* __restrict__ qkv, float* __restrict__ mask)
{
    int b = blockIdx.x;
    __shared__ float q197[CDIM];
    int tid = threadIdx.x;
    const __half* qrow = qkv + ((size_t)b*NSEQ + 197)*(3*CDIM);
    for (int i=tid;i<CDIM;i+=256) q197[i]=__half2float(qrow[i]);
    __syncthreads();
    int warp=tid>>5, lane=tid&31;
    for (int k=warp; k<NSEQ; k+=8){
        const __half* krow = qkv + ((size_t)b*NSEQ + k)*(3*CDIM) + CDIM;
        float s=0.f;
        for (int d=lane; d<CDIM; d+=32) s = fmaf(q197[d], __half2float(krow[d]), s);
#pragma unroll
        for (int o=16;o;o>>=1) s += __shfl_xor_sync(0xffffffffu, s, o);
        if (lane==0) mask[(size_t)b*NSEQ + k] = 1.f/(1.f + __expf(-s*(0.125f/12.f)));
    }
}

// ---------------- fused mma.sync attention per (b,h), 512 threads ----------------
#define ATT_SMEM (166400 + 29952 + 29952)
__global__ void __launch_bounds__(512) attn_mma(
    const __half* __restrict__ qkv, const float* __restrict__ mask,
    int use_mask, __half* __restrict__ O)
{
    int bh = blockIdx.x;
    int b = bh / NHEAD, h = bh - b*NHEAD;
    extern __shared__ char smem[];
    float*  Ss = (float*)smem;                    // [208][200] fp32
    __half* Qs = (__half*)(smem + 166400);        // [208][72]
    __half* Ks = (__half*)(smem + 166400+29952);  // [208][72]
    const int tid=threadIdx.x, warp=tid>>5, lane=tid&31;
    const int gid=lane>>2, tg=lane&3;
    const __half* base = qkv + (size_t)b*NSEQ*(3*CDIM) + h*HD;
    const __half hz = __float2half(0.f);

    for (int i = tid; i < 208*64; i += 512){
        int t = i>>6, d = i&63;
        __half q = hz, k = hz;
        if (t < NSEQ){
            q = base[(size_t)t*(3*CDIM) + d];
            k = base[(size_t)t*(3*CDIM) + CDIM + d];
        }
        Qs[t*72+d] = q; Ks[t*72+d] = k;
    }
    __syncthreads();

    // scores: 13 m-tiles over 16 warps
    for (int mt = warp; mt < 13; mt += 16){
        int m0 = mt*16;
        unsigned af[4][4];
#pragma unroll
        for (int ks=0; ks<4; ks++){
            int kb = ks*16 + 2*tg;
            af[ks][0] = *(const unsigned*)&Qs[(m0+gid  )*72 + kb  ];
            af[ks][1] = *(const unsigned*)&Qs[(m0+gid+8)*72 + kb  ];
            af[ks][2] = *(const unsigned*)&Qs[(m0+gid  )*72 + kb+8];
            af[ks][3] = *(const unsigned*)&Qs[(m0+gid+8)*72 + kb+8];
        }
        for (int nt = 0; nt < 25; nt++){
            int n0 = nt*8;
            float acc[4] = {0.f,0.f,0.f,0.f};
#pragma unroll
            for (int ks=0; ks<4; ks++){
                int kb = ks*16 + 2*tg;
                unsigned bb[2];
                bb[0] = *(const unsigned*)&Ks[(n0+gid)*72 + kb  ];
                bb[1] = *(const unsigned*)&Ks[(n0+gid)*72 + kb+8];
                mma_fp16(acc, af[ks], bb);
            }
            int r = m0 + gid, c = n0 + tg*2;
            Ss[(size_t)r*200 + c  ] = acc[0]*0.125f;
            Ss[(size_t)r*200 + c+1] = acc[1]*0.125f;
            Ss[(size_t)(r+8)*200 + c  ] = acc[2]*0.125f;
            Ss[(size_t)(r+8)*200 + c+1] = acc[3]*0.125f;
        }
    }
    __syncthreads();

    __half* Vs = Qs;    // V transposed overwrites Q
    for (int i = tid; i < 64*216; i += 512){
        int d = i/216, k = i - d*216;
        __half v = hz;
        if (k < NSEQ) v = base[(size_t)k*(3*CDIM) + 2*CDIM + d];
        Vs[d*216 + k] = v;
    }
    const float* mrow = mask + (size_t)b*NSEQ;
    for (int row = warp; row < NSEQ; row += 16){
        float* Sr = Ss + (size_t)row*200;
        float v[7]; float mx = -1e30f;
#pragma unroll
        for (int j=0;j<7;j++){
            int col = lane + 32*j;
            v[j] = (col < NSEQ) ? Sr[col] : -1e30f;
            mx = fmaxf(mx, v[j]);
        }
#pragma unroll
        for (int o=16;o;o>>=1) mx = fmaxf(mx, __shfl_xor_sync(0xffffffffu, mx, o));
        float sum = 0.f;
#pragma unroll
        for (int j=0;j<7;j++){
            int col = lane + 32*j;
            v[j] = (col < NSEQ) ? __expf(v[j]-mx) : 0.f;
            sum += v[j];
        }
#pragma unroll
        for (int o=16;o;o>>=1) sum += __shfl_xor_sync(0xffffffffu, sum, o);
        float inv = 1.f/sum;
#pragma unroll
        for (int j=0;j<7;j++){
            int col = lane + 32*j;
            if (col < NSEQ){
                float p = v[j]*inv;
                if (use_mask) p *= mrow[col];
                Sr[col] = p;
            }
        }
        if (lane < 2) Sr[NSEQ + lane] = 0.f;
    }
    __syncthreads();

    // O = P V : 13 m-tiles over 16 warps
    __half* Oh = O + (size_t)b*NSEQ*CDIM + h*HD;
    for (int mt = warp; mt < 13; mt += 16){
        int m0 = mt*16;
        float acc[8][4];
#pragma unroll
        for (int j=0;j<8;j++)
#pragma unroll
            for (int q=0;q<4;q++) acc[j][q]=0.f;
        for (int ks = 0; ks < 12; ks++){
            int k0 = ks*16 + 2*tg;
            unsigned af[4];
            {
                float2 p0 = *(const float2*)&Ss[(size_t)(m0+gid  )*200 + k0  ];
                float2 p1 = *(const float2*)&Ss[(size_t)(m0+gid+8)*200 + k0  ];
                float2 p2 = *(const float2*)&Ss[(size_t)(m0+gid  )*200 + k0+8];
                float2 p3 = *(const float2*)&Ss[(size_t)(m0+gid+8)*200 + k0+8];
                __half2 h0=__floats2half2_rn(p0.x,p0.y), h1=__floats2half2_rn(p1.x,p1.y);
                __half2 h2=__floats2half2_rn(p2.x,p2.y), h3=__floats2half2_rn(p3.x,p3.y);
                af[0]=*(unsigned*)&h0; af[1]=*(unsigned*)&h1;
                af[2]=*(unsigned*)&h2; af[3]=*(unsigned*)&h3;
            }
#pragma unroll
            for (int nt = 0; nt < 8; nt++){
                unsigned bb[2];
                bb[0] = *(const unsigned*)&Vs[(nt*8+gid)*216 + k0  ];
                bb[1] = *(const unsigned*)&Vs[(nt*8+gid)*216 + k0+8];
                mma_fp16(acc[nt], af, bb);
            }
        }
        {
            int k0 = 192 + 2*tg;
            float2 p0 = *(const float2*)&Ss[(size_t)(m0+gid  )*200 + k0];
            float2 p1 = *(const float2*)&Ss[(size_t)(m0+gid+8)*200 + k0];
            __half2 h0=__floats2half2_rn(p0.x,p0.y), h1=__floats2half2_rn(p1.x,p1.y);
            unsigned af2[2]; af2[0]=*(unsigned*)&h0; af2[1]=*(unsigned*)&h1;
#pragma unroll
            for (int nt = 0; nt < 8; nt++){
                unsigned b0 = *(const unsigned*)&Vs[(nt*8+gid)*216 + k0];
                mma_fp16_k8(acc[nt], af2, b0);
            }
        }
#pragma unroll
        for (int rr = 0; rr < 2; rr++){
            int q = m0 + gid + rr*8;
            if (q < NSEQ){
#pragma unroll
                for (int nt = 0; nt < 8; nt++){
                    *(__half2*)&Oh[(size_t)q*CDIM + nt*8 + tg*2] =
                        __floats2half2_rn(acc[nt][rr*2], acc[nt][rr*2+1]);
                }
            }
        }
    }
}

// ---------------- head features: 9 rectangle sums per (b,c) ----------------
__launch_bounds__(256)
__global__ void sfeat_kernel(const __half* __restrict__ T, float* __restrict__ SF)
{
    int i = blockIdx.x*256 + threadIdx.x;
    if (i >= NB*CDIM) return;
    int b = i / CDIM, c = i - b*CDIM;
    const __half* base = T + ((size_t)b*NSEQ + 1)*CDIM + c;
    float tot=0.f, r0=0.f, r13=0.f, c0s=0.f, c13s=0.f;
    for (int u=0; u<14; u++) {
        for (int v=0; v<14; v++) {
            float val = __half2float(base[(size_t)(u*14+v)*CDIM]);
            tot += val;
            if (u==0)  r0  += val;
            if (u==13) r13 += val;
            if (v==0)  c0s += val;
            if (v==13) c13s += val;
        }
    }
    float x00 = __half2float(base[0]);
    float x0e = __half2float(base[(size_t)13*CDIM]);
    float xe0 = __half2float(base[(size_t)(13*14)*CDIM]);
    float xee = __half2float(base[(size_t)(13*14+13)*CDIM]);
    float* o = SF + (size_t)b*6912 + c*9;
    for (int dy=0; dy<3; dy++)
        for (int dx=0; dx<3; dx++) {
            float s = tot;
            if (dy==0) s -= r13;
            if (dy==2) s -= r0;
            if (dx==0) s -= c13s;
            if (dx==2) s -= c0s;
            if (dy==0 && dx==0) s += xee;
            if (dy==0 && dx==2) s += xe0;
            if (dy==2 && dx==0) s += x0e;
            if (dy==2 && dx==2) s += x00;
            o[dy*3+dx] = s;
        }
}

// ---------------- logits ----------------
__launch_bounds__(256)
__global__ void head_kernel(const float* __restrict__ SF, const float* __restrict__ W,
                            const float* __restrict__ bias, float* __restrict__ out)
{
    int gw = (blockIdx.x*256 + threadIdx.x) >> 5;
    int lane = threadIdx.x & 31;
    if (gw >= NB*200) return;
    int b = gw / 200, cls = gw - b*200;
    const float* a = SF + (size_t)b*6912;
    const float* w = W + (size_t)cls*6912;
    float s = 0.f;
    for (int k = lane; k < 6912; k += 32) s = fmaf(a[k], w[k], s);
#pragma unroll
    for (int o=16;o;o>>=1) s += __shfl_xor_sync(0xffffffffu, s, o);
    if (lane==0) out[gw] = s*(1.f/196.f) + bias[cls];
}

// ---------------- final mask outputs ----------------
__launch_bounds__(256)
__global__ void final_mask(const float* __restrict__ Mlayers, const float* __restrict__ gk,
                           float* __restrict__ out)
{
    int b = blockIdx.x;
    __shared__ float ma[196];
    __shared__ float red[8];
    int tid = threadIdx.x;
    if (tid < 196) {
        float s = 0.f;
        for (int l=9; l<12; l++) s += Mlayers[((size_t)l*NB + b)*NSEQ + 1 + tid];
        ma[tid] = s * (1.f/3.f);
    }
    __syncthreads();
    float part = (tid < 196) ? ma[tid] : 0.f;
#pragma unroll
    for (int o=16;o;o>>=1) part += __shfl_xor_sync(0xffffffffu, part, o);
    if ((tid&31)==0) red[tid>>5] = part;
    __syncthreads();
    if (tid==0){ float t=0.f; for(int i=0;i<8;i++) t+=red[i]; out[12800 + b] = t*(1.f/196.f); }
    float t3 = 0.f;
    if (tid < 196) {
        int y = tid/14, x = tid - y*14;
        float m = 0.f;
        for (int dy=0; dy<3; dy++)
            for (int dx=0; dx<3; dx++) {
                int yy = y+dy-1, xx = x+dx-1;
                if (yy>=0 && yy<14 && xx>=0 && xx<14)
                    m += gk[dy*3+dx]*ma[yy*14+xx];
            }
        t3 = (1.f - m)*m;
    }
    __syncthreads();
#pragma unroll
    for (int o=16;o;o>>=1) t3 += __shfl_xor_sync(0xffffffffu, t3, o);
    if ((tid&31)==0) red[tid>>5] = t3;
    __syncthreads();
    if (tid==0){ float t=0.f; for(int i=0;i<8;i++) t+=red[i]; out[12864 + b] = t*(1.f/196.f); }
}

// ---------------- launch ----------------
extern "C" void kernel_launch(void* const* d_in, const int* in_sizes, int n_in,
                              void* d_out, int out_size)
{
    const float* x       = (const float*)d_in[0];
    const float* patch_w = (const float*)d_in[1];
    const float* patch_b = (const float*)d_in[2];
    const float* cls_tok = (const float*)d_in[3];
    const float* loc_tok = (const float*)d_in[4];
    const float* pos_emb = (const float*)d_in[5];
    const float* loc_emb = (const float*)d_in[6];
    const float* ln1_w   = (const float*)d_in[7];
    const float* ln1_b   = (const float*)d_in[8];
    const float* qkv_w   = (const float*)d_in[9];
    const float* proj_w  = (const float*)d_in[10];
    const float* proj_b  = (const float*)d_in[11];
    const float* ln2_w   = (const float*)d_in[12];
    const float* ln2_b   = (const float*)d_in[13];
    const float* fc1_w   = (const float*)d_in[14];
    const float* fc1_b   = (const float*)d_in[15];
    const float* fc2_w   = (const float*)d_in[16];
    const float* fc2_b   = (const float*)d_in[17];
    const float* norm_w  = (const float*)d_in[18];
    const float* norm_b  = (const float*)d_in[19];
    const float* head_w  = (const float*)d_in[20];
    const float* head_b  = (const float*)d_in[21];
    const float* gk      = (const float*)d_in[22];
    float* out = (float*)d_out;

    float *t, *o, *maskb, *sfeat;
    __half *ah, *qkvh, *oh, *hh, *wh;
    cudaGetSymbolAddress((void**)&t,     g_t);
    cudaGetSymbolAddress((void**)&o,     g_o);
    cudaGetSymbolAddress((void**)&maskb, g_mask);
    cudaGetSymbolAddress((void**)&sfeat, g_sfeat);
    cudaGetSymbolAddress((void**)&ah,    g_ah);
    cudaGetSymbolAddress((void**)&qkvh,  g_qkvh);
    cudaGetSymbolAddress((void**)&oh,    g_oh);
    cudaGetSymbolAddress((void**)&hh,    g_hh);
    cudaGetSymbolAddress((void**)&wh,    g_wh);

    cudaFuncSetAttribute(attn_mma, cudaFuncAttributeMaxDynamicSharedMemorySize, ATT_SMEM);
    cudaFuncSetAttribute(gemm_h2<EP_BIAS,float>,       cudaFuncAttributeMaxDynamicSharedMemorySize, G_SMEM);
    cudaFuncSetAttribute(gemm_h2<EP_NONE,__half>,      cudaFuncAttributeMaxDynamicSharedMemorySize, G_SMEM);
    cudaFuncSetAttribute(gemm_h2<EP_BIAS_RES,float>,   cudaFuncAttributeMaxDynamicSharedMemorySize, G_SMEM);
    cudaFuncSetAttribute(gemm_h2<EP_BIAS_GELU,__half>, cudaFuncAttributeMaxDynamicSharedMemorySize, G_SMEM);

    // convert weights to fp16 pool (must run every call; inputs may change)
    f2h_kernel<<<(589824/4+255)/256,   256>>>(patch_w, wh + W_PATCH, 589824/4);
    f2h_kernel<<<(21233664/4+255)/256, 256>>>(qkv_w,   wh + W_QKV,   21233664/4);
    f2h_kernel<<<(7077888/4+255)/256,  256>>>(proj_w,  wh + W_PROJ,  7077888/4);
    f2h_kernel<<<(28311552/4+255)/256, 256>>>(fc1_w,   wh + W_FC1,   28311552/4);
    f2h_kernel<<<(28311552/4+255)/256, 256>>>(fc2_w,   wh + W_FC2,   28311552/4);

    // patch embed
    im2col_patch<<<(NPAT*CDIM+255)/256, 256>>>(x, ah);
    gemm_h2<EP_BIAS,float><<<dim3(6,98), 256, G_SMEM>>>(ah, wh + W_PATCH, patch_b, nullptr, o, NPAT, CDIM, CDIM);
    assemble_t<<<(NTOK*CDIM+255)/256, 256>>>(o, cls_tok, loc_tok, pos_emb, loc_emb, t);

    for (int d=0; d<12; d++) {
        ln_kernel<<<NTOK, 256>>>(t, ln1_w + d*CDIM, ln1_b + d*CDIM, ah);
        gemm_h2<EP_NONE,__half><<<dim3(18,99), 256, G_SMEM>>>(ah, wh + W_QKV + (size_t)d*3*CDIM*CDIM,
                                                              nullptr, nullptr, qkvh, NTOK, 3*CDIM, CDIM);
        if (d >= 9)
            mask_pre<<<NB, 256>>>(qkvh, maskb + (size_t)d*NB*NSEQ);
        attn_mma<<<NB*NHEAD, 512, ATT_SMEM>>>(qkvh, maskb + (size_t)d*NB*NSEQ, (d>=9)?1:0, oh);
        gemm_h2<EP_BIAS_RES,float><<<dim3(6,99), 256, G_SMEM>>>(oh, wh + W_PROJ + (size_t)d*CDIM*CDIM,
                                                                proj_b + d*CDIM, t, t, NTOK, CDIM, CDIM);
        ln_kernel<<<NTOK, 256>>>(t, ln2_w + d*CDIM, ln2_b + d*CDIM, ah);
        gemm_h2<EP_BIAS_GELU,__half><<<dim3(24,99), 256, G_SMEM>>>(ah, wh + W_FC1 + (size_t)d*4*CDIM*CDIM,
                                                                   fc1_b + d*4*CDIM, nullptr, hh, NTOK, 4*CDIM, CDIM);
        gemm_h2<EP_BIAS_RES,float><<<dim3(6,99), 256, G_SMEM>>>(hh, wh + W_FC2 + (size_t)d*CDIM*4*CDIM,
                                                                fc2_b + d*CDIM, t, t, NTOK, CDIM, 4*CDIM);
    }

    ln_kernel<<<NTOK, 256>>>(t, norm_w, norm_b, ah);
    sfeat_kernel<<<(NB*CDIM+255)/256, 256>>>(ah, sfeat);
    head_kernel<<<(NB*200*32+255)/256, 256>>>(sfeat, head_w, head_b, out);
    final_mask<<<NB, 256>>>(maskb, gk, out);
}

// round 8
// speedup vs baseline: 6.9193x; 1.0617x over previous
#include <cuda_runtime.h>
#include <cuda_fp16.h>
#include <math.h>
#include <stdint.h>

// ---------------- problem constants ----------------
#define NB    64
#define NSEQ  198
#define NTOK  (NB*NSEQ)      // 12672 = 99*128 = 1584*8
#define NPAT  (NB*196)       // 12544 = 98*128
#define CDIM  768
#define NHEAD 12
#define HD    64

// weight fp16 pool offsets
#define W_PATCH 0
#define W_QKV   589824
#define W_PROJ  21823488
#define W_FC1   28901376
#define W_FC2   57212928
#define W_TOTAL 85524480

// ---------------- scratch (device globals; no allocs allowed) ----------------
__device__ float  g_t   [(size_t)NTOK*CDIM];
__device__ float  g_o   [(size_t)NTOK*CDIM];
__device__ float  g_mask[(size_t)12*NB*NSEQ];
__device__ float  g_sfeat[(size_t)NB*6912];
__device__ __half g_ah  [(size_t)NTOK*CDIM];
__device__ __half g_qkvh[(size_t)NTOK*3*CDIM];
__device__ __half g_oh  [(size_t)NTOK*CDIM];
__device__ __half g_hh  [(size_t)NTOK*4*CDIM];
__device__ __half g_wh  [(size_t)W_TOTAL];

enum { EP_NONE=0, EP_BIAS=1, EP_BIAS_RES=2, EP_BIAS_GELU=3 };

// ---------------- helpers ----------------
__device__ __forceinline__ uint32_t smem_u32(const void* p){
    uint32_t a;
    asm("{ .reg .u64 t; cvta.to.shared.u64 t, %1; cvt.u32.u64 %0, t; }" : "=r"(a) : "l"(p));
    return a;
}
__device__ __forceinline__ void mma_fp16(float c[4], const unsigned a[4], const unsigned b[2]){
    asm volatile("mma.sync.aligned.m16n8k16.row.col.f32.f16.f16.f32 "
        "{%0,%1,%2,%3}, {%4,%5,%6,%7}, {%8,%9}, {%0,%1,%2,%3};\n"
        : "+f"(c[0]),"+f"(c[1]),"+f"(c[2]),"+f"(c[3])
        : "r"(a[0]),"r"(a[1]),"r"(a[2]),"r"(a[3]), "r"(b[0]),"r"(b[1]));
}
__device__ __forceinline__ void ldsm_x4(unsigned r[4], uint32_t a){
    asm volatile("ldmatrix.sync.aligned.m8n8.x4.shared.b16 {%0,%1,%2,%3}, [%4];"
        : "=r"(r[0]),"=r"(r[1]),"=r"(r[2]),"=r"(r[3]) : "r"(a));
}
__device__ __forceinline__ void cp16(uint32_t s, const void* g){
    asm volatile("cp.async.cg.shared.global [%0], [%1], 16;" :: "r"(s), "l"(g));
}
#define CP_COMMIT() asm volatile("cp.async.commit_group;" ::: "memory")
#define CP_WAIT(n)  asm volatile("cp.async.wait_group %0;" :: "n"(n) : "memory")

// ---------------- f32 -> f16 convert ----------------
__global__ void f2h_kernel(const float* __restrict__ src, __half* __restrict__ dst, int n4){
    int i = blockIdx.x*256 + threadIdx.x;
    if (i < n4){
        float4 v = ((const float4*)src)[i];
        ((__half2*)dst)[i*2  ] = __floats2half2_rn(v.x, v.y);
        ((__half2*)dst)[i*2+1] = __floats2half2_rn(v.z, v.w);
    }
}

// ---------------- pipelined fp16 GEMM-NT: C[M,N] = A[M,K]*B[N,K]^T ----------------
#define GSTAGES      4
#define GSTAGE_BYTES 20480
#define G_SMEM       (GSTAGES*GSTAGE_BYTES)   // 81920
template<int EPI, typename OT>
__global__ void __launch_bounds__(256,2) gemm_h2(
    const __half* __restrict__ A, const __half* __restrict__ B,
    const float* __restrict__ bias, const float* __restrict__ res,
    OT* __restrict__ C, int M, int N, int K)
{
    extern __shared__ char smem[];
    const uint32_t sb = smem_u32(smem);
    const int tid=threadIdx.x, warp=tid>>5, lane=tid&31;
    const int wm=warp>>1, wn=warp&1;
    const int gid=lane>>2, tg=lane&3;
    const int bm=blockIdx.y*128, bn=blockIdx.x*128;

    const int lrow = tid>>2, lseg = tid&3;
    const __half* Ag = A + (size_t)(bm+lrow)*K + lseg*8;
    const __half* Bg = B + (size_t)(bn+lrow)*K + lseg*8;
    const uint32_t sOffA0 = (uint32_t)lrow*80 + lseg*16;
    const uint32_t sOffA1 = (uint32_t)(lrow+64)*80 + lseg*16;

    const uint32_t aBase = sb + (uint32_t)((wm*32 + (lane&15))*80 + (lane>>4)*16);
    const uint32_t bBase = sb + 10240u +
        (uint32_t)((wn*64 + (lane&7) + ((lane>>4)&1)*8)*80 + ((lane>>3)&1)*16);

    float acc[2][8][4];
#pragma unroll
    for(int i=0;i<2;i++)
#pragma unroll
        for(int j=0;j<8;j++)
#pragma unroll
            for(int q=0;q<4;q++) acc[i][j][q]=0.f;

    const int nit = K >> 5;

#pragma unroll
    for (int s=0; s<3; s++){
        uint32_t st = sb + (uint32_t)s*GSTAGE_BYTES;
        size_t koff = (size_t)s*32;
        cp16(st + sOffA0,          Ag + koff);
        cp16(st + sOffA1,          Ag + (size_t)64*K + koff);
        cp16(st + 10240 + sOffA0,  Bg + koff);
        cp16(st + 10240 + sOffA1,  Bg + (size_t)64*K + koff);
        CP_COMMIT();
    }

    for (int it=0; it<nit; it++){
        if (it < nit-3)       CP_WAIT(2);
        else if (it == nit-2) CP_WAIT(1);
        else if (it == nit-1) CP_WAIT(0);
        else                  CP_WAIT(2);
        __syncthreads();
        if (it + 3 < nit){
            int ss = (it+3) & 3;
            uint32_t st = sb + (uint32_t)ss*GSTAGE_BYTES;
            size_t koff = (size_t)(it+3)*32;
            cp16(st + sOffA0,          Ag + koff);
            cp16(st + sOffA1,          Ag + (size_t)64*K + koff);
            cp16(st + 10240 + sOffA0,  Bg + koff);
            cp16(st + 10240 + sOffA1,  Bg + (size_t)64*K + koff);
            CP_COMMIT();
        }
        const uint32_t stoff = (uint32_t)(it & 3)*GSTAGE_BYTES;
#pragma unroll
        for (int ks=0; ks<2; ks++){
            unsigned af0[4], af1[4];
            ldsm_x4(af0, aBase + stoff + ks*32);
            ldsm_x4(af1, aBase + stoff + 1280 + ks*32);
#pragma unroll
            for (int jp=0; jp<4; jp++){
                unsigned bf[4];
                ldsm_x4(bf, bBase + stoff + (uint32_t)jp*1280 + ks*32);
                mma_fp16(acc[0][2*jp  ], af0, bf);
                mma_fp16(acc[0][2*jp+1], af0, bf+2);
                mma_fp16(acc[1][2*jp  ], af1, bf);
                mma_fp16(acc[1][2*jp+1], af1, bf+2);
            }
        }
    }

#pragma unroll
    for(int i=0;i<2;i++){
#pragma unroll
        for(int rr=0;rr<2;rr++){
            int row = bm + wm*32 + i*16 + gid + rr*8;
#pragma unroll
            for(int j=0;j<8;j++){
                int col = bn + wn*64 + j*8 + tg*2;
                float v0 = acc[i][j][rr*2+0];
                float v1 = acc[i][j][rr*2+1];
                if (EPI == EP_BIAS) { v0 += bias[col]; v1 += bias[col+1]; }
                else if (EPI == EP_BIAS_RES) {
                    v0 += bias[col]   + res[(size_t)row*N+col];
                    v1 += bias[col+1] + res[(size_t)row*N+col+1];
                }
                else if (EPI == EP_BIAS_GELU) {
                    v0 += bias[col];   v1 += bias[col+1];
                    v0 = 0.5f*v0*(1.f + erff(v0*0.70710678118654752f));
                    v1 = 0.5f*v1*(1.f + erff(v1*0.70710678118654752f));
                }
                if (sizeof(OT)==2) {
                    *(__half2*)((__half*)C + (size_t)row*N + col) = __floats2half2_rn(v0, v1);
                } else {
                    *(float2*)((float*)C + (size_t)row*N + col) = make_float2(v0, v1);
                }
            }
        }
    }
}

// ---------------- patch im2col -> fp16 ----------------
__global__ void im2col_patch(const float* __restrict__ x, __half* __restrict__ A)
{
    int i = blockIdx.x*256 + threadIdx.x;
    if (i >= NPAT*CDIM) return;
    int p = i / CDIM, kidx = i - p*CDIM;
    int b = p / 196, pp = p - b*196;
    int py = pp / 14, px = pp - py*14;
    int c = kidx >> 8;
    int rem = kidx & 255;
    int iy = rem >> 4, ix = rem & 15;
    A[i] = __float2half(x[(((size_t)b*3 + c)*224 + (py*16+iy))*224 + (px*16+ix)]);
}

// ---------------- assemble token stream ----------------
__global__ void assemble_t(const float* __restrict__ P, const float* __restrict__ cls,
                           const float* __restrict__ loc, const float* __restrict__ pos,
                           const float* __restrict__ loce, float* __restrict__ T)
{
    int i = blockIdx.x*256 + threadIdx.x;
    if (i >= NTOK*CDIM) return;
    int tok = i / CDIM, c = i - tok*CDIM;
    int b = tok / NSEQ, tt = tok - b*NSEQ;
    float v;
    if (tt == 0)          v = cls[c] + pos[c];
    else if (tt == 197)   v = loc[c] + loce[c];
    else                  v = P[((size_t)b*196 + tt-1)*CDIM + c] + pos[(size_t)tt*CDIM + c];
    T[i] = v;
}

// ---------------- layernorm: warp per row, fp32 in, fp16 out ----------------
__launch_bounds__(256)
__global__ void ln_kernel(const float* __restrict__ X, const float* __restrict__ w,
                          const float* __restrict__ bb, __half* __restrict__ Y)
{
    int row = blockIdx.x*8 + (threadIdx.x>>5);
    int lane = threadIdx.x & 31;
    const float4* x4 = (const float4*)(X + (size_t)row*CDIM);
    float4 v[6];
    float s = 0.f;
#pragma unroll
    for (int i=0;i<6;i++){
        v[i] = x4[lane + 32*i];
        s += v[i].x + v[i].y + v[i].z + v[i].w;
    }
#pragma unroll
    for (int o=16;o;o>>=1) s += __shfl_xor_sync(0xffffffffu, s, o);
    float m = s * (1.f/768.f);
    float q = 0.f;
#pragma unroll
    for (int i=0;i<6;i++){
        float d0=v[i].x-m, d1=v[i].y-m, d2=v[i].z-m, d3=v[i].w-m;
        q += d0*d0 + d1*d1 + d2*d2 + d3*d3;
    }
#pragma unroll
    for (int o=16;o;o>>=1) q += __shfl_xor_sync(0xffffffffu, q, o);
    float rs = rsqrtf(q*(1.f/768.f) + 1e-5f);
    __half* y = Y + (size_t)row*CDIM;
#pragma unroll
    for (int i=0;i<6;i++){
        int col = (lane + 32*i)*4;
        float4 wv = *(const float4*)(w + col);
        float4 bv = *(const float4*)(bb + col);
        __half2 h0 = __floats2half2_rn((v[i].x-m)*rs*wv.x + bv.x, (v[i].y-m)*rs*wv.y + bv.y);
        __half2 h1 = __floats2half2_rn((v[i].z-m)*rs*wv.z + bv.z, (v[i].w-m)*rs*wv.w + bv.w);
        *(__half2*)(y + col)     = h0;
        *(__half2*)(y + col + 2) = h1;
    }
}

// ---------------- mask precompute (fp16 qkv) ----------------
__launch_bounds__(256)
__global__ void mask_pre(const __half* __restrict__ qkv, float* __restrict__ mask)
{
    int b = blockIdx.x;
    __shared__ float q197[CDIM];
    int tid = threadIdx.x;
    const __half* qrow = qkv + ((size_t)b*NSEQ + 197)*(3*CDIM);
    for (int i=tid;i<CDIM;i+=256) q197[i]=__half2float(qrow[i]);
    __syncthreads();
    int warp=tid>>5, lane=tid&31;
    for (int k=warp; k<NSEQ; k+=8){
        const __half* krow = qkv + ((size_t)b*NSEQ + k)*(3*CDIM) + CDIM;
        float s=0.f;
        for (int d=lane; d<CDIM; d+=32) s = fmaf(q197[d], __half2float(krow[d]), s);
#pragma unroll
        for (int o=16;o;o>>=1) s += __shfl_xor_sync(0xffffffffu, s, o);
        if (lane==0) mask[(size_t)b*NSEQ + k] = 1.f/(1.f + __expf(-s*(0.125f/12.f)));
    }
}

// ---------------- flash attention per (b,h): online softmax, no S smem ----------------
// smem: Qs [208][72] fp16 | Ks [208][72] fp16 | Vs [64][216] fp16 | msk [208] f32
#define ATT_SMEM (29952 + 29952 + 27648 + 832)   // 88384
__global__ void __launch_bounds__(256,2) attn_flash(
    const __half* __restrict__ qkv, const float* __restrict__ mask,
    int use_mask, __half* __restrict__ O)
{
    int bh = blockIdx.x;
    int b = bh / NHEAD, h = bh - b*NHEAD;
    extern __shared__ char smem[];
    __half* Qs = (__half*)smem;                   // [208][72]
    __half* Ks = (__half*)(smem + 29952);         // [208][72]
    __half* Vs = (__half*)(smem + 59904);         // [64][216]  (V transposed: [d][k])
    float*  msk = (float*)(smem + 87552);         // [208]
    const int tid=threadIdx.x, warp=tid>>5, lane=tid&31;
    const int gid=lane>>2, tg=lane&3;
    const __half* base = qkv + (size_t)b*NSEQ*(3*CDIM) + h*HD;
    const __half hz = __float2half(0.f);

    for (int i = tid; i < 208*64; i += 256){
        int t = i>>6, d = i&63;
        __half q = hz, k = hz;
        if (t < NSEQ){
            q = base[(size_t)t*(3*CDIM) + d];
            k = base[(size_t)t*(3*CDIM) + CDIM + d];
        }
        Qs[t*72+d] = q; Ks[t*72+d] = k;
    }
    for (int i = tid; i < 64*216; i += 256){
        int d = i/216, k = i - d*216;
        __half v = hz;
        if (k < NSEQ) v = base[(size_t)k*(3*CDIM) + 2*CDIM + d];
        Vs[d*216 + k] = v;
    }
    if (tid < 208)
        msk[tid] = (tid < NSEQ) ? (use_mask ? mask[(size_t)b*NSEQ + tid] : 1.f) : 0.f;
    __syncthreads();

    __half* Oh = O + (size_t)b*NSEQ*CDIM + h*HD;
    for (int mt = warp; mt < 13; mt += 8){
        int m0 = mt*16;
        // Q fragments (constant over k-tiles)
        unsigned af[4][4];
#pragma unroll
        for (int ks=0; ks<4; ks++){
            int kb = ks*16 + 2*tg;
            af[ks][0] = *(const unsigned*)&Qs[(m0+gid  )*72 + kb  ];
            af[ks][1] = *(const unsigned*)&Qs[(m0+gid+8)*72 + kb  ];
            af[ks][2] = *(const unsigned*)&Qs[(m0+gid  )*72 + kb+8];
            af[ks][3] = *(const unsigned*)&Qs[(m0+gid+8)*72 + kb+8];
        }
        float accO[8][4];
#pragma unroll
        for (int nt=0;nt<8;nt++)
#pragma unroll
            for (int q2=0;q2<4;q2++) accO[nt][q2]=0.f;
        float m0r = -1e30f, m1r = -1e30f, l0r = 0.f, l1r = 0.f;

        for (int kt = 0; kt < 13; kt++){
            int n0 = kt*16;
            // scores for two 8-wide n-tiles
            float s[2][4];
#pragma unroll
            for (int t2=0; t2<2; t2++){
                float a4[4] = {0.f,0.f,0.f,0.f};
#pragma unroll
                for (int ks=0; ks<4; ks++){
                    int kb = ks*16 + 2*tg;
                    unsigned bb[2];
                    bb[0] = *(const unsigned*)&Ks[(n0+t2*8+gid)*72 + kb  ];
                    bb[1] = *(const unsigned*)&Ks[(n0+t2*8+gid)*72 + kb+8];
                    mma_fp16(a4, af[ks], bb);
                }
                int c0 = n0 + t2*8 + 2*tg;
                s[t2][0] = (c0   < NSEQ) ? a4[0]*0.125f : -1e30f;
                s[t2][1] = (c0+1 < NSEQ) ? a4[1]*0.125f : -1e30f;
                s[t2][2] = (c0   < NSEQ) ? a4[2]*0.125f : -1e30f;
                s[t2][3] = (c0+1 < NSEQ) ? a4[3]*0.125f : -1e30f;
            }
            // row max (quad reduce over tg lanes)
            float tm0 = fmaxf(fmaxf(s[0][0], s[0][1]), fmaxf(s[1][0], s[1][1]));
            float tm1 = fmaxf(fmaxf(s[0][2], s[0][3]), fmaxf(s[1][2], s[1][3]));
            tm0 = fmaxf(tm0, __shfl_xor_sync(0xffffffffu, tm0, 1));
            tm0 = fmaxf(tm0, __shfl_xor_sync(0xffffffffu, tm0, 2));
            tm1 = fmaxf(tm1, __shfl_xor_sync(0xffffffffu, tm1, 1));
            tm1 = fmaxf(tm1, __shfl_xor_sync(0xffffffffu, tm1, 2));
            float mn0 = fmaxf(m0r, tm0), mn1 = fmaxf(m1r, tm1);
            float sc0 = __expf(m0r - mn0), sc1 = __expf(m1r - mn1);
            // p = exp(s - m); row sums
            float p[2][4];
#pragma unroll
            for (int t2=0; t2<2; t2++){
                p[t2][0] = __expf(s[t2][0] - mn0);
                p[t2][1] = __expf(s[t2][1] - mn0);
                p[t2][2] = __expf(s[t2][2] - mn1);
                p[t2][3] = __expf(s[t2][3] - mn1);
            }
            float ls0 = p[0][0]+p[0][1]+p[1][0]+p[1][1];
            float ls1 = p[0][2]+p[0][3]+p[1][2]+p[1][3];
            ls0 += __shfl_xor_sync(0xffffffffu, ls0, 1);
            ls0 += __shfl_xor_sync(0xffffffffu, ls0, 2);
            ls1 += __shfl_xor_sync(0xffffffffu, ls1, 1);
            ls1 += __shfl_xor_sync(0xffffffffu, ls1, 2);
            l0r = l0r*sc0 + ls0;
            l1r = l1r*sc1 + ls1;
            m0r = mn0; m1r = mn1;
            // rescale O accumulators
#pragma unroll
            for (int nt=0; nt<8; nt++){
                accO[nt][0]*=sc0; accO[nt][1]*=sc0;
                accO[nt][2]*=sc1; accO[nt][3]*=sc1;
            }
            // apply attention mask (post-softmax numerator) and pack P frags
            unsigned ap[4];
            {
                int c0 = n0 + 2*tg, c1 = n0 + 8 + 2*tg;
                float mk00 = msk[c0], mk01 = msk[c0+1];
                float mk10 = msk[c1], mk11 = msk[c1+1];
                __half2 h0 = __floats2half2_rn(p[0][0]*mk00, p[0][1]*mk01);
                __half2 h1 = __floats2half2_rn(p[0][2]*mk00, p[0][3]*mk01);
                __half2 h2 = __floats2half2_rn(p[1][0]*mk10, p[1][1]*mk11);
                __half2 h3 = __floats2half2_rn(p[1][2]*mk10, p[1][3]*mk11);
                ap[0]=*(unsigned*)&h0; ap[1]=*(unsigned*)&h1;
                ap[2]=*(unsigned*)&h2; ap[3]=*(unsigned*)&h3;
            }
            // accumulate PV
            int kv = n0 + 2*tg;
#pragma unroll
            for (int nt=0; nt<8; nt++){
                unsigned bb[2];
                bb[0] = *(const unsigned*)&Vs[(nt*8+gid)*216 + kv  ];
                bb[1] = *(const unsigned*)&Vs[(nt*8+gid)*216 + kv+8];
                mma_fp16(accO[nt], ap, bb);
            }
        }
        // epilogue: divide by l, write fp16
        float inv0 = 1.f/l0r, inv1 = 1.f/l1r;
        int q0 = m0 + gid, q1 = m0 + gid + 8;
        if (q0 < NSEQ){
#pragma unroll
            for (int nt=0; nt<8; nt++)
                *(__half2*)&Oh[(size_t)q0*CDIM + nt*8 + tg*2] =
                    __floats2half2_rn(accO[nt][0]*inv0, accO[nt][1]*inv0);
        }
        if (q1 < NSEQ){
#pragma unroll
            for (int nt=0; nt<8; nt++)
                *(__half2*)&Oh[(size_t)q1*CDIM + nt*8 + tg*2] =
                    __floats2half2_rn(accO[nt][2]*inv1, accO[nt][3]*inv1);
        }
    }
}

// ---------------- head features: 9 rectangle sums per (b,c) ----------------
__launch_bounds__(256)
__global__ void sfeat_kernel(const __half* __restrict__ T, float* __restrict__ SF)
{
    int i = blockIdx.x*256 + threadIdx.x;
    if (i >= NB*CDIM) return;
    int b = i / CDIM, c = i - b*CDIM;
    const __half* base = T + ((size_t)b*NSEQ + 1)*CDIM + c;
    float tot=0.f, r0=0.f, r13=0.f, c0s=0.f, c13s=0.f;
    for (int u=0; u<14; u++) {
        for (int v=0; v<14; v++) {
            float val = __half2float(base[(size_t)(u*14+v)*CDIM]);
            tot += val;
            if (u==0)  r0  += val;
            if (u==13) r13 += val;
            if (v==0)  c0s += val;
            if (v==13) c13s += val;
        }
    }
    float x00 = __half2float(base[0]);
    float x0e = __half2float(base[(size_t)13*CDIM]);
    float xe0 = __half2float(base[(size_t)(13*14)*CDIM]);
    float xee = __half2float(base[(size_t)(13*14+13)*CDIM]);
    float* o = SF + (size_t)b*6912 + c*9;
    for (int dy=0; dy<3; dy++)
        for (int dx=0; dx<3; dx++) {
            float s = tot;
            if (dy==0) s -= r13;
            if (dy==2) s -= r0;
            if (dx==0) s -= c13s;
            if (dx==2) s -= c0s;
            if (dy==0 && dx==0) s += xee;
            if (dy==0 && dx==2) s += xe0;
            if (dy==2 && dx==0) s += x0e;
            if (dy==2 && dx==2) s += x00;
            o[dy*3+dx] = s;
        }
}

// ---------------- logits ----------------
__launch_bounds__(256)
__global__ void head_kernel(const float* __restrict__ SF, const float* __restrict__ W,
                            const float* __restrict__ bias, float* __restrict__ out)
{
    int gw = (blockIdx.x*256 + threadIdx.x) >> 5;
    int lane = threadIdx.x & 31;
    if (gw >= NB*200) return;
    int b = gw / 200, cls = gw - b*200;
    const float* a = SF + (size_t)b*6912;
    const float* w = W + (size_t)cls*6912;
    float s = 0.f;
    for (int k = lane; k < 6912; k += 32) s = fmaf(a[k], w[k], s);
#pragma unroll
    for (int o=16;o;o>>=1) s += __shfl_xor_sync(0xffffffffu, s, o);
    if (lane==0) out[gw] = s*(1.f/196.f) + bias[cls];
}

// ---------------- final mask outputs ----------------
__launch_bounds__(256)
__global__ void final_mask(const float* __restrict__ Mlayers, const float* __restrict__ gk,
                           float* __restrict__ out)
{
    int b = blockIdx.x;
    __shared__ float ma[196];
    __shared__ float red[8];
    int tid = threadIdx.x;
    if (tid < 196) {
        float s = 0.f;
        for (int l=9; l<12; l++) s += Mlayers[((size_t)l*NB + b)*NSEQ + 1 + tid];
        ma[tid] = s * (1.f/3.f);
    }
    __syncthreads();
    float part = (tid < 196) ? ma[tid] : 0.f;
#pragma unroll
    for (int o=16;o;o>>=1) part += __shfl_xor_sync(0xffffffffu, part, o);
    if ((tid&31)==0) red[tid>>5] = part;
    __syncthreads();
    if (tid==0){ float t=0.f; for(int i=0;i<8;i++) t+=red[i]; out[12800 + b] = t*(1.f/196.f); }
    float t3 = 0.f;
    if (tid < 196) {
        int y = tid/14, x = tid - y*14;
        float m = 0.f;
        for (int dy=0; dy<3; dy++)
            for (int dx=0; dx<3; dx++) {
                int yy = y+dy-1, xx = x+dx-1;
                if (yy>=0 && yy<14 && xx>=0 && xx<14)
                    m += gk[dy*3+dx]*ma[yy*14+xx];
            }
        t3 = (1.f - m)*m;
    }
    __syncthreads();
#pragma unroll
    for (int o=16;o;o>>=1) t3 += __shfl_xor_sync(0xffffffffu, t3, o);
    if ((tid&31)==0) red[tid>>5] = t3;
    __syncthreads();
    if (tid==0){ float t=0.f; for(int i=0;i<8;i++) t+=red[i]; out[12864 + b] = t*(1.f/196.f); }
}

// ---------------- launch ----------------
extern "C" void kernel_launch(void* const* d_in, const int* in_sizes, int n_in,
                              void* d_out, int out_size)
{
    const float* x       = (const float*)d_in[0];
    const float* patch_w = (const float*)d_in[1];
    const float* patch_b = (const float*)d_in[2];
    const float* cls_tok = (const float*)d_in[3];
    const float* loc_tok = (const float*)d_in[4];
    const float* pos_emb = (const float*)d_in[5];
    const float* loc_emb = (const float*)d_in[6];
    const float* ln1_w   = (const float*)d_in[7];
    const float* ln1_b   = (const float*)d_in[8];
    const float* qkv_w   = (const float*)d_in[9];
    const float* proj_w  = (const float*)d_in[10];
    const float* proj_b  = (const float*)d_in[11];
    const float* ln2_w   = (const float*)d_in[12];
    const float* ln2_b   = (const float*)d_in[13];
    const float* fc1_w   = (const float*)d_in[14];
    const float* fc1_b   = (const float*)d_in[15];
    const float* fc2_w   = (const float*)d_in[16];
    const float* fc2_b   = (const float*)d_in[17];
    const float* norm_w  = (const float*)d_in[18];
    const float* norm_b  = (const float*)d_in[19];
    const float* head_w  = (const float*)d_in[20];
    const float* head_b  = (const float*)d_in[21];
    const float* gk      = (const float*)d_in[22];
    float* out = (float*)d_out;

    float *t, *o, *maskb, *sfeat;
    __half *ah, *qkvh, *oh, *hh, *wh;
    cudaGetSymbolAddress((void**)&t,     g_t);
    cudaGetSymbolAddress((void**)&o,     g_o);
    cudaGetSymbolAddress((void**)&maskb, g_mask);
    cudaGetSymbolAddress((void**)&sfeat, g_sfeat);
    cudaGetSymbolAddress((void**)&ah,    g_ah);
    cudaGetSymbolAddress((void**)&qkvh,  g_qkvh);
    cudaGetSymbolAddress((void**)&oh,    g_oh);
    cudaGetSymbolAddress((void**)&hh,    g_hh);
    cudaGetSymbolAddress((void**)&wh,    g_wh);

    cudaFuncSetAttribute(attn_flash, cudaFuncAttributeMaxDynamicSharedMemorySize, ATT_SMEM);
    cudaFuncSetAttribute(gemm_h2<EP_BIAS,float>,       cudaFuncAttributeMaxDynamicSharedMemorySize, G_SMEM);
    cudaFuncSetAttribute(gemm_h2<EP_NONE,__half>,      cudaFuncAttributeMaxDynamicSharedMemorySize, G_SMEM);
    cudaFuncSetAttribute(gemm_h2<EP_BIAS_RES,float>,   cudaFuncAttributeMaxDynamicSharedMemorySize, G_SMEM);
    cudaFuncSetAttribute(gemm_h2<EP_BIAS_GELU,__half>, cudaFuncAttributeMaxDynamicSharedMemorySize, G_SMEM);

    // convert weights to fp16 pool (must run every call; inputs may change)
    f2h_kernel<<<(589824/4+255)/256,   256>>>(patch_w, wh + W_PATCH, 589824/4);
    f2h_kernel<<<(21233664/4+255)/256, 256>>>(qkv_w,   wh + W_QKV,   21233664/4);
    f2h_kernel<<<(7077888/4+255)/256,  256>>>(proj_w,  wh + W_PROJ,  7077888/4);
    f2h_kernel<<<(28311552/4+255)/256, 256>>>(fc1_w,   wh + W_FC1,   28311552/4);
    f2h_kernel<<<(28311552/4+255)/256, 256>>>(fc2_w,   wh + W_FC2,   28311552/4);

    // patch embed
    im2col_patch<<<(NPAT*CDIM+255)/256, 256>>>(x, ah);
    gemm_h2<EP_BIAS,float><<<dim3(6,98), 256, G_SMEM>>>(ah, wh + W_PATCH, patch_b, nullptr, o, NPAT, CDIM, CDIM);
    assemble_t<<<(NTOK*CDIM+255)/256, 256>>>(o, cls_tok, loc_tok, pos_emb, loc_emb, t);

    for (int d=0; d<12; d++) {
        ln_kernel<<<NTOK/8, 256>>>(t, ln1_w + d*CDIM, ln1_b + d*CDIM, ah);
        gemm_h2<EP_NONE,__half><<<dim3(18,99), 256, G_SMEM>>>(ah, wh + W_QKV + (size_t)d*3*CDIM*CDIM,
                                                              nullptr, nullptr, qkvh, NTOK, 3*CDIM, CDIM);
        if (d >= 9)
            mask_pre<<<NB, 256>>>(qkvh, maskb + (size_t)d*NB*NSEQ);
        attn_flash<<<NB*NHEAD, 256, ATT_SMEM>>>(qkvh, maskb + (size_t)d*NB*NSEQ, (d>=9)?1:0, oh);
        gemm_h2<EP_BIAS_RES,float><<<dim3(6,99), 256, G_SMEM>>>(oh, wh + W_PROJ + (size_t)d*CDIM*CDIM,
                                                                proj_b + d*CDIM, t, t, NTOK, CDIM, CDIM);
        ln_kernel<<<NTOK/8, 256>>>(t, ln2_w + d*CDIM, ln2_b + d*CDIM, ah);
        gemm_h2<EP_BIAS_GELU,__half><<<dim3(24,99), 256, G_SMEM>>>(ah, wh + W_FC1 + (size_t)d*4*CDIM*CDIM,
                                                                   fc1_b + d*4*CDIM, nullptr, hh, NTOK, 4*CDIM, CDIM);
        gemm_h2<EP_BIAS_RES,float><<<dim3(6,99), 256, G_SMEM>>>(hh, wh + W_FC2 + (size_t)d*CDIM*4*CDIM,
                                                                fc2_b + d*CDIM, t, t, NTOK, CDIM, 4*CDIM);
    }

    ln_kernel<<<NTOK/8, 256>>>(t, norm_w, norm_b, ah);
    sfeat_kernel<<<(NB*CDIM+255)/256, 256>>>(ah, sfeat);
    head_kernel<<<(NB*200*32+255)/256, 256>>>(sfeat, head_w, head_b, out);
    final_mask<<<NB, 256>>>(maskb, gk, out);
}